// round 2
// baseline (speedup 1.0000x reference)
#include <cuda_runtime.h>
#include <math.h>
#include <stdint.h>

#define NXI 512
#define LDIM 128
#define NSTATES 128
#define NIN 64
#define HDIM 1152           // 2*NXI + LDIM
#define BATCHN 32768
#define EPSV 0.001f
#define NEWTON_ITERS 22

// ---------------- device scratch (static allocation; no cudaMalloc) ----------------
__device__ float g_H[HDIM * HDIM];
__device__ float g_E[NXI * NXI];
__device__ float g_Za[NXI * NXI];
__device__ float g_Zb[NXI * NXI];
__device__ float g_T[NXI * NXI];
__device__ float g_R[NXI * 768];          // [Fm | B1 | B2]
__device__ float g_Wpre[LDIM * 640];      // [-H21 | D12]
__device__ float g_Wout[576 * 768];       // rows 0..63: [C2|D21|D22]; rows 64..575: Einv*[Fm|B1|B2]
__device__ float g_D11[LDIM * LDIM];
__device__ float g_LamInv[LDIM];
__device__ float g_rows[NXI];
__device__ float g_fro2inv;
__device__ float g_pre[(size_t)BATCHN * LDIM];
__device__ float g_eps[(size_t)BATCHN * LDIM];

// ---------------- generic small GEMM: C = op(A) * op(B), 64x64x16 tiles ----------------
// TA: A is (K x M), access A[k*lda+m]. else A is (M x K): A[m*lda+k].
// TB: B is (N x K), access B[n*ldb+k]. else B is (K x N): B[k*ldb+n].
// emode 0: C = acc ; 1: C = 2*D - acc (Newton) ; 2: C = acc + EPSV on diagonal
template <bool TA, bool TB>
__global__ __launch_bounds__(256) void gemm64(const float* __restrict__ A,
                                              const float* __restrict__ B,
                                              float* __restrict__ C,
                                              int M, int N, int K,
                                              int lda, int ldb, int ldc,
                                              const float* __restrict__ D, int emode) {
    __shared__ float As[16][65];
    __shared__ float Bs[16][65];
    int tid = threadIdx.x;
    int tx = tid & 15, ty = tid >> 4;
    int m0 = blockIdx.y * 64, n0 = blockIdx.x * 64;
    float acc[4][4] = {};
    for (int k0 = 0; k0 < K; k0 += 16) {
        __syncthreads();
#pragma unroll
        for (int r = 0; r < 4; ++r) {
            int idx = tid + r * 256;
            if (TA) {
                int k = idx >> 6, m = idx & 63;
                As[k][m] = A[(size_t)(k0 + k) * lda + m0 + m];
            } else {
                int m = idx >> 4, k = idx & 15;
                As[k][m] = A[(size_t)(m0 + m) * lda + k0 + k];
            }
            if (TB) {
                int n = idx >> 4, k = idx & 15;
                Bs[k][n] = B[(size_t)(n0 + n) * ldb + k0 + k];
            } else {
                int k = idx >> 6, n = idx & 63;
                Bs[k][n] = B[(size_t)(k0 + k) * ldb + n0 + n];
            }
        }
        __syncthreads();
#pragma unroll
        for (int k = 0; k < 16; ++k) {
            float av[4], bv[4];
#pragma unroll
            for (int i = 0; i < 4; ++i) av[i] = As[k][ty * 4 + i];
#pragma unroll
            for (int j = 0; j < 4; ++j) bv[j] = Bs[k][tx * 4 + j];
#pragma unroll
            for (int i = 0; i < 4; ++i)
#pragma unroll
                for (int j = 0; j < 4; ++j) acc[i][j] = fmaf(av[i], bv[j], acc[i][j]);
        }
    }
#pragma unroll
    for (int i = 0; i < 4; ++i) {
        int m = m0 + ty * 4 + i;
#pragma unroll
        for (int j = 0; j < 4; ++j) {
            int n = n0 + tx * 4 + j;
            float v = acc[i][j];
            if (emode == 1) v = 2.0f * D[(size_t)m * ldc + n] - v;
            else if (emode == 2 && m == n) v += EPSV;
            C[(size_t)m * ldc + n] = v;
        }
    }
}

// ---------------- batch GEMM: out(M x N) = [A0|A1|A2](M x Ktot) * W(N x Ktot)^T ----------------
// 128x64 block tile, BK=16, 256 threads, 8x4 per-thread tile.
__global__ __launch_bounds__(256) void gemm_batch(
    const float* __restrict__ A0, const float* __restrict__ A1, const float* __restrict__ A2,
    int K0, int K01, int Ktot,
    const float* __restrict__ W, int N,
    float* __restrict__ out0, float* __restrict__ out1, int mode) {
    __shared__ float As[16][132];
    __shared__ float Bs[16][68];
    int tid = threadIdx.x;
    int m0 = blockIdx.y * 128;
    int n0 = blockIdx.x * 64;
    int tx = tid & 15, ty = tid >> 4;
    int lr = tid >> 2, lq = tid & 3;
    float acc[8][4] = {};
    for (int k0 = 0; k0 < Ktot; k0 += 16) {
        const float* Ap; int lda, kb;
        if (k0 < K0)        { Ap = A0; lda = K0;         kb = k0; }
        else if (k0 < K01)  { Ap = A1; lda = K01 - K0;   kb = k0 - K0; }
        else                { Ap = A2; lda = Ktot - K01; kb = k0 - K01; }
        float4 a0 = *(const float4*)(Ap + (size_t)(m0 + lr) * lda + kb + lq * 4);
        float4 a1 = *(const float4*)(Ap + (size_t)(m0 + lr + 64) * lda + kb + lq * 4);
        float4 bw = *(const float4*)(W + (size_t)(n0 + lr) * Ktot + k0 + lq * 4);
        __syncthreads();
        As[lq * 4 + 0][lr] = a0.x; As[lq * 4 + 1][lr] = a0.y;
        As[lq * 4 + 2][lr] = a0.z; As[lq * 4 + 3][lr] = a0.w;
        As[lq * 4 + 0][lr + 64] = a1.x; As[lq * 4 + 1][lr + 64] = a1.y;
        As[lq * 4 + 2][lr + 64] = a1.z; As[lq * 4 + 3][lr + 64] = a1.w;
        Bs[lq * 4 + 0][lr] = bw.x; Bs[lq * 4 + 1][lr] = bw.y;
        Bs[lq * 4 + 2][lr] = bw.z; Bs[lq * 4 + 3][lr] = bw.w;
        __syncthreads();
#pragma unroll
        for (int k = 0; k < 16; ++k) {
            float4 av0 = *(const float4*)&As[k][ty * 8];
            float4 av1 = *(const float4*)&As[k][ty * 8 + 4];
            float4 bv = *(const float4*)&Bs[k][tx * 4];
            float a[8] = {av0.x, av0.y, av0.z, av0.w, av1.x, av1.y, av1.z, av1.w};
            float b[4] = {bv.x, bv.y, bv.z, bv.w};
#pragma unroll
            for (int i = 0; i < 8; ++i)
#pragma unroll
                for (int j = 0; j < 4; ++j) acc[i][j] = fmaf(a[i], b[j], acc[i][j]);
        }
    }
#pragma unroll
    for (int i = 0; i < 8; ++i) {
        int m = m0 + ty * 8 + i;
#pragma unroll
        for (int j = 0; j < 4; ++j) {
            int n = n0 + tx * 4 + j;
            float v = acc[i][j];
            if (mode == 0) {
                out0[(size_t)m * N + n] = v;
            } else {
                if (n < NIN) out0[(size_t)m * NIN + n] = v;
                else out1[(size_t)m * NXI + (n - NIN)] = v;
            }
        }
    }
}

// ---------------- parameter builders ----------------
__global__ void build_E(const float* __restrict__ Y) {
    int idx = blockIdx.x * blockDim.x + threadIdx.x;
    if (idx >= NXI * NXI) return;
    int i = idx >> 9, j = idx & 511;
    g_E[idx] = 0.5f * (g_H[(size_t)i * HDIM + j] + g_H[(size_t)(640 + i) * HDIM + 640 + j] +
                       Y[(size_t)i * NXI + j] - Y[(size_t)j * NXI + i]);
}
__global__ void build_Wpre(const float* __restrict__ D12) {
    int idx = blockIdx.x * blockDim.x + threadIdx.x;
    if (idx >= LDIM * 640) return;
    int r = idx / 640, c = idx - r * 640;
    g_Wpre[idx] = (c < NXI) ? -g_H[(size_t)(NXI + r) * HDIM + c]
                            : D12[r * NSTATES + (c - NXI)];
}
__global__ void build_D11() {
    int idx = blockIdx.x * blockDim.x + threadIdx.x;
    if (idx >= LDIM * LDIM) return;
    int i = idx >> 7, j = idx & 127;
    g_D11[idx] = (j < i) ? -g_H[(size_t)(NXI + i) * HDIM + NXI + j] : 0.0f;
    if (j == i) g_LamInv[i] = 2.0f / g_H[(size_t)(NXI + i) * HDIM + NXI + i];
}
__global__ void build_R(const float* __restrict__ B2) {
    int idx = blockIdx.x * blockDim.x + threadIdx.x;
    if (idx >= NXI * 768) return;
    int i = idx / 768, c = idx - i * 768;
    g_R[idx] = (c < 640) ? g_H[(size_t)(640 + i) * HDIM + c] : B2[i * NSTATES + (c - 640)];
}
__global__ void build_WoutTop(const float* __restrict__ C2, const float* __restrict__ D21,
                              const float* __restrict__ D22) {
    int idx = blockIdx.x * blockDim.x + threadIdx.x;
    if (idx >= NIN * 768) return;
    int r = idx / 768, c = idx - r * 768;
    g_Wout[idx] = (c < NXI) ? C2[r * NXI + c]
                            : (c < 640 ? D21[r * LDIM + (c - NXI)] : D22[r * NSTATES + (c - 640)]);
}

// ---------------- deterministic Frobenius norm + Newton init ----------------
__global__ void rowsq_kernel() {
    int i = blockIdx.x;
    float s = 0.0f;
    for (int j = threadIdx.x; j < NXI; j += 256) {
        float v = g_E[(size_t)i * NXI + j];
        s = fmaf(v, v, s);
    }
    __shared__ float red[256];
    red[threadIdx.x] = s;
    __syncthreads();
    for (int o = 128; o > 0; o >>= 1) {
        if (threadIdx.x < o) red[threadIdx.x] += red[threadIdx.x + o];
        __syncthreads();
    }
    if (threadIdx.x == 0) g_rows[i] = red[0];
}
__global__ void finfro_kernel() {
    __shared__ float red[512];
    red[threadIdx.x] = g_rows[threadIdx.x];
    __syncthreads();
    for (int o = 256; o > 0; o >>= 1) {
        if (threadIdx.x < o) red[threadIdx.x] += red[threadIdx.x + o];
        __syncthreads();
    }
    if (threadIdx.x == 0) g_fro2inv = 1.0f / red[0];
}
__global__ void initZ_kernel() {
    int idx = blockIdx.x * blockDim.x + threadIdx.x;
    if (idx >= NXI * NXI) return;
    int i = idx >> 9, j = idx & 511;
    g_Za[idx] = g_E[(size_t)j * NXI + i] * g_fro2inv;
}

// ---------------- tanh forward-substitution scan ----------------
// eps[b,i] = tanh( (pre[b,i] + sum_{j<i} eps[b,j]*D11[i,j]) / Lam[i] )
__global__ __launch_bounds__(64) void eps_kernel() {
    __shared__ float es[128 * 64];
    __shared__ float li[128];
    int tid = threadIdx.x;
    size_t b = (size_t)blockIdx.x * 64 + tid;
    for (int i = tid; i < 128; i += 64) li[i] = g_LamInv[i];
    __syncthreads();
    for (int i = 0; i < 128; ++i) {
        float v = g_pre[b * 128 + i];
        const float* __restrict__ dr = &g_D11[i * 128];
        float v0 = 0.f, v1 = 0.f, v2 = 0.f, v3 = 0.f;
        int j = 0;
        for (; j + 3 < i; j += 4) {
            v0 = fmaf(es[(j + 0) * 64 + tid], dr[j + 0], v0);
            v1 = fmaf(es[(j + 1) * 64 + tid], dr[j + 1], v1);
            v2 = fmaf(es[(j + 2) * 64 + tid], dr[j + 2], v2);
            v3 = fmaf(es[(j + 3) * 64 + tid], dr[j + 3], v3);
        }
        for (; j < i; ++j) v0 = fmaf(es[j * 64 + tid], dr[j], v0);
        v += (v0 + v1) + (v2 + v3);
        float e = tanhf(v * li[i]);
        es[i * 64 + tid] = e;
        g_eps[b * 128 + i] = e;
    }
}

// ---------------- launch ----------------
extern "C" void kernel_launch(void* const* d_in, const int* in_sizes, int n_in,
                              void* d_out, int out_size) {
    (void)in_sizes; (void)n_in;
    const float* w   = (const float*)d_in[1];
    const float* xi  = (const float*)d_in[2];
    const float* X   = (const float*)d_in[3];
    const float* Y   = (const float*)d_in[4];
    const float* B2  = (const float*)d_in[5];
    const float* C2  = (const float*)d_in[6];
    const float* D21 = (const float*)d_in[7];
    const float* D22 = (const float*)d_in[8];
    const float* D12 = (const float*)d_in[9];
    float* out   = (float*)d_out;
    float* out_u = out;                                 // (B,1,64)
    float* out_x = out + (size_t)BATCHN * NIN;          // (B,1,512)
    (void)out_size;

    float *pH, *pE, *pZa, *pZb, *pT, *pR, *pWout, *pWpre, *pPre, *pEps;
    cudaGetSymbolAddress((void**)&pH, g_H);
    cudaGetSymbolAddress((void**)&pE, g_E);
    cudaGetSymbolAddress((void**)&pZa, g_Za);
    cudaGetSymbolAddress((void**)&pZb, g_Zb);
    cudaGetSymbolAddress((void**)&pT, g_T);
    cudaGetSymbolAddress((void**)&pR, g_R);
    cudaGetSymbolAddress((void**)&pWout, g_Wout);
    cudaGetSymbolAddress((void**)&pWpre, g_Wpre);
    cudaGetSymbolAddress((void**)&pPre, g_pre);
    cudaGetSymbolAddress((void**)&pEps, g_eps);

    // 1) H = X^T X + eps*I
    gemm64<true, false><<<dim3(HDIM / 64, HDIM / 64), 256>>>(
        X, X, pH, HDIM, HDIM, HDIM, HDIM, HDIM, HDIM, nullptr, 2);

    // 2) derived parameter matrices
    build_E<<<(NXI * NXI + 255) / 256, 256>>>(Y);
    build_Wpre<<<(LDIM * 640 + 255) / 256, 256>>>(D12);
    build_D11<<<(LDIM * LDIM + 255) / 256, 256>>>();
    build_R<<<(NXI * 768 + 255) / 256, 256>>>(B2);
    build_WoutTop<<<(NIN * 768 + 255) / 256, 256>>>(C2, D21, D22);

    // 3) Newton-Schulz inverse of E: Z0 = E^T/||E||_F^2 ; Z <- 2Z - Z(EZ)
    rowsq_kernel<<<NXI, 256>>>();
    finfro_kernel<<<1, 512>>>();
    initZ_kernel<<<(NXI * NXI + 255) / 256, 256>>>();
    float* Zc = pZa;
    float* Zn = pZb;
    for (int it = 0; it < NEWTON_ITERS; ++it) {
        gemm64<false, false><<<dim3(8, 8), 256>>>(
            pE, Zc, pT, NXI, NXI, NXI, NXI, NXI, NXI, nullptr, 0);
        gemm64<false, false><<<dim3(8, 8), 256>>>(
            Zc, pT, Zn, NXI, NXI, NXI, NXI, NXI, NXI, Zc, 1);
        float* tmp = Zc; Zc = Zn; Zn = tmp;
    }

    // 4) Wout rows 64..575 = Einv @ [Fm|B1|B2]
    gemm64<false, false><<<dim3(768 / 64, NXI / 64), 256>>>(
        Zc, pR, pWout + 64 * 768, NXI, 768, NXI, NXI, 768, 768, nullptr, 0);

    // 5) pre = [xi|w] @ Wpre^T     (M=32768, N=128, K=640)
    gemm_batch<<<dim3(128 / 64, BATCHN / 128), 256>>>(
        xi, w, w, NXI, 640, 640, pWpre, 128, pPre, nullptr, 0);

    // 6) tanh forward substitution
    eps_kernel<<<BATCHN / 64, 64>>>();

    // 7) [u | xi_] = [xi|eps|w] @ Wout^T   (M=32768, N=576, K=768)
    gemm_batch<<<dim3(576 / 64, BATCHN / 128), 256>>>(
        xi, pEps, w, NXI, 640, 768, pWout, 576, out_u, out_x, 1);
}

// round 3
// speedup vs baseline: 1.2610x; 1.2610x over previous
#include <cuda_runtime.h>
#include <math.h>
#include <stdint.h>

#define NXI 512
#define LDIM 128
#define NSTATES 128
#define NIN 64
#define HDIM 1152           // 2*NXI + LDIM
#define BATCHN 32768
#define EPSV 0.001f
#define ALPHA 0.55f
#define NEWTON_ITERS 9      // + fused first step = 10 squarings

// ---------------- device scratch (static allocation; no cudaMalloc) ----------------
__device__ float g_H[HDIM * HDIM];
__device__ float g_M[NXI * NXI];          // D^-1 E
__device__ float g_Za[NXI * NXI];
__device__ float g_Zb[NXI * NXI];
__device__ float g_T[NXI * NXI];
__device__ float g_R[NXI * 768];          // D^-1 [Fm | B1 | B2]
__device__ float g_Wpre[LDIM * 640];      // [-H21 | D12]
__device__ float g_Wout[640 * 768];       // rows 0..63: [C2|D21|D22]; 64..575: Einv*[Fm|B1|B2]; 576..639: zero pad
__device__ float g_D11[LDIM * LDIM];
__device__ float g_LamInv[LDIM];
__device__ float g_dinv[NXI];
__device__ float g_pre[(size_t)BATCHN * LDIM];
__device__ float g_eps[(size_t)BATCHN * LDIM];

// ---------------- generic small GEMM: C = op(A) * op(B), 64x64x16 tiles ----------------
// TA: A is (K x M): A[k*lda+m]; else (M x K): A[m*lda+k].
// TB: B is (N x K): B[n*ldb+k]; else (K x N): B[k*ldb+n].
// emode 0: C = acc ; 1: C = 2*D - acc (Newton) ; 2: C = acc + EPSV on diagonal
template <bool TA, bool TB>
__global__ __launch_bounds__(256) void gemm64(const float* __restrict__ A,
                                              const float* __restrict__ B,
                                              float* __restrict__ C,
                                              int M, int N, int K,
                                              int lda, int ldb, int ldc,
                                              const float* __restrict__ D, int emode) {
    __shared__ float As[16][65];
    __shared__ float Bs[16][65];
    int tid = threadIdx.x;
    int tx = tid & 15, ty = tid >> 4;
    int m0 = blockIdx.y * 64, n0 = blockIdx.x * 64;
    float acc[4][4] = {};
    for (int k0 = 0; k0 < K; k0 += 16) {
        __syncthreads();
#pragma unroll
        for (int r = 0; r < 4; ++r) {
            int idx = tid + r * 256;
            if (TA) {
                int k = idx >> 6, m = idx & 63;
                As[k][m] = A[(size_t)(k0 + k) * lda + m0 + m];
            } else {
                int m = idx >> 4, k = idx & 15;
                As[k][m] = A[(size_t)(m0 + m) * lda + k0 + k];
            }
            if (TB) {
                int n = idx >> 4, k = idx & 15;
                Bs[k][n] = B[(size_t)(n0 + n) * ldb + k0 + k];
            } else {
                int k = idx >> 6, n = idx & 63;
                Bs[k][n] = B[(size_t)(k0 + k) * ldb + n0 + n];
            }
        }
        __syncthreads();
#pragma unroll
        for (int k = 0; k < 16; ++k) {
            float av[4], bv[4];
#pragma unroll
            for (int i = 0; i < 4; ++i) av[i] = As[k][ty * 4 + i];
#pragma unroll
            for (int j = 0; j < 4; ++j) bv[j] = Bs[k][tx * 4 + j];
#pragma unroll
            for (int i = 0; i < 4; ++i)
#pragma unroll
                for (int j = 0; j < 4; ++j) acc[i][j] = fmaf(av[i], bv[j], acc[i][j]);
        }
    }
#pragma unroll
    for (int i = 0; i < 4; ++i) {
        int m = m0 + ty * 4 + i;
#pragma unroll
        for (int j = 0; j < 4; ++j) {
            int n = n0 + tx * 4 + j;
            float v = acc[i][j];
            if (emode == 1) v = 2.0f * D[(size_t)m * ldc + n] - v;
            else if (emode == 2 && m == n) v += EPSV;
            C[(size_t)m * ldc + n] = v;
        }
    }
}

// ---------------- big batch GEMM: out(M x N) = [A0|A1|A2](M x Ktot) * W(N x Ktot)^T ----------
// 128x128 block tile, BK=16, 256 threads, 8x8 per-thread tile, global prefetch overlap.
__global__ __launch_bounds__(256, 2) void gemm_batch128(
    const float* __restrict__ A0, const float* __restrict__ A1, const float* __restrict__ A2,
    int K0, int K01, int Ktot,
    const float* __restrict__ W, int Nout,
    float* __restrict__ out0, float* __restrict__ out1, int mode) {
    __shared__ float As[16][128];
    __shared__ float Bs[16][128];
    const int tid = threadIdx.x;
    const int tx = tid & 15, ty = tid >> 4;
    const int lr = tid & 127;        // m (A) or n (B) index for loads
    const int lq = tid >> 7;         // k-half: 0 -> k[0:8), 1 -> k[8:16)
    const size_t m0 = (size_t)blockIdx.y * 128;
    const int n0 = blockIdx.x * 128;

    float acc[8][8] = {};
    float4 ar0, ar1, br0, br1;

    auto loadA = [&](int kc) {
        const float* Ap; int lda, kb;
        if (kc < K0)       { Ap = A0; lda = K0;         kb = kc; }
        else if (kc < K01) { Ap = A1; lda = K01 - K0;   kb = kc - K0; }
        else               { Ap = A2; lda = Ktot - K01; kb = kc - K01; }
        const float* p = Ap + (m0 + lr) * (size_t)lda + kb + lq * 8;
        ar0 = *(const float4*)p;
        ar1 = *(const float4*)(p + 4);
    };
    auto loadB = [&](int kc) {
        const float* p = W + (size_t)(n0 + lr) * Ktot + kc + lq * 8;
        br0 = *(const float4*)p;
        br1 = *(const float4*)(p + 4);
    };

    loadA(0);
    loadB(0);

    for (int kc = 0; kc < Ktot; kc += 16) {
        const int kb = lq * 8;
        As[kb + 0][lr] = ar0.x; As[kb + 1][lr] = ar0.y;
        As[kb + 2][lr] = ar0.z; As[kb + 3][lr] = ar0.w;
        As[kb + 4][lr] = ar1.x; As[kb + 5][lr] = ar1.y;
        As[kb + 6][lr] = ar1.z; As[kb + 7][lr] = ar1.w;
        Bs[kb + 0][lr] = br0.x; Bs[kb + 1][lr] = br0.y;
        Bs[kb + 2][lr] = br0.z; Bs[kb + 3][lr] = br0.w;
        Bs[kb + 4][lr] = br1.x; Bs[kb + 5][lr] = br1.y;
        Bs[kb + 6][lr] = br1.z; Bs[kb + 7][lr] = br1.w;
        __syncthreads();
        if (kc + 16 < Ktot) { loadA(kc + 16); loadB(kc + 16); }
#pragma unroll
        for (int k = 0; k < 16; ++k) {
            float4 a0 = *(const float4*)&As[k][ty * 8];
            float4 a1 = *(const float4*)&As[k][ty * 8 + 4];
            float4 b0 = *(const float4*)&Bs[k][tx * 8];
            float4 b1 = *(const float4*)&Bs[k][tx * 8 + 4];
            float a[8] = {a0.x, a0.y, a0.z, a0.w, a1.x, a1.y, a1.z, a1.w};
            float b[8] = {b0.x, b0.y, b0.z, b0.w, b1.x, b1.y, b1.z, b1.w};
#pragma unroll
            for (int i = 0; i < 8; ++i)
#pragma unroll
                for (int j = 0; j < 8; ++j) acc[i][j] = fmaf(a[i], b[j], acc[i][j]);
        }
        __syncthreads();
    }
#pragma unroll
    for (int i = 0; i < 8; ++i) {
        size_t m = m0 + ty * 8 + i;
#pragma unroll
        for (int j = 0; j < 8; ++j) {
            int n = n0 + tx * 8 + j;
            if (n >= Nout) continue;
            float v = acc[i][j];
            if (mode == 0) {
                out0[m * Nout + n] = v;
            } else {
                if (n < NIN) out0[m * NIN + n] = v;
                else out1[m * NXI + (n - NIN)] = v;
            }
        }
    }
}

// ---------------- parameter builders ----------------
__global__ void diag_kernel() {
    int i = blockIdx.x * blockDim.x + threadIdx.x;
    if (i >= NXI) return;
    g_dinv[i] = 2.0f / (g_H[(size_t)i * HDIM + i] + g_H[(size_t)(640 + i) * HDIM + 640 + i]);
}
// M = D^-1 * E ; Z1 = 2*ALPHA*I - ALPHA^2 * M   (fused first Newton step, Z0 = ALPHA*I)
__global__ void build_MZ(const float* __restrict__ Y) {
    int idx = blockIdx.x * blockDim.x + threadIdx.x;
    if (idx >= NXI * NXI) return;
    int i = idx >> 9, j = idx & 511;
    float e = 0.5f * (g_H[(size_t)i * HDIM + j] + g_H[(size_t)(640 + i) * HDIM + 640 + j] +
                      Y[(size_t)i * NXI + j] - Y[(size_t)j * NXI + i]);
    float m = g_dinv[i] * e;
    g_M[idx] = m;
    g_Za[idx] = ((i == j) ? 2.0f * ALPHA : 0.0f) - ALPHA * ALPHA * m;
}
__global__ void build_Wpre(const float* __restrict__ D12) {
    int idx = blockIdx.x * blockDim.x + threadIdx.x;
    if (idx >= LDIM * 640) return;
    int r = idx / 640, c = idx - r * 640;
    g_Wpre[idx] = (c < NXI) ? -g_H[(size_t)(NXI + r) * HDIM + c]
                            : D12[r * NSTATES + (c - NXI)];
}
__global__ void build_D11() {
    int idx = blockIdx.x * blockDim.x + threadIdx.x;
    if (idx >= LDIM * LDIM) return;
    int i = idx >> 7, j = idx & 127;
    g_D11[idx] = (j < i) ? -g_H[(size_t)(NXI + i) * HDIM + NXI + j] : 0.0f;
    if (j == i) g_LamInv[i] = 2.0f / g_H[(size_t)(NXI + i) * HDIM + NXI + i];
}
// R = D^-1 [Fm | B1 | B2]  (row-scaled so Minv @ R = Einv @ [Fm|B1|B2])
__global__ void build_R(const float* __restrict__ B2) {
    int idx = blockIdx.x * blockDim.x + threadIdx.x;
    if (idx >= NXI * 768) return;
    int i = idx / 768, c = idx - i * 768;
    float v = (c < 640) ? g_H[(size_t)(640 + i) * HDIM + c] : B2[i * NSTATES + (c - 640)];
    g_R[idx] = g_dinv[i] * v;
}
__global__ void build_WoutTop(const float* __restrict__ C2, const float* __restrict__ D21,
                              const float* __restrict__ D22) {
    int idx = blockIdx.x * blockDim.x + threadIdx.x;
    if (idx >= NIN * 768) return;
    int r = idx / 768, c = idx - r * 768;
    g_Wout[idx] = (c < NXI) ? C2[r * NXI + c]
                            : (c < 640 ? D21[r * LDIM + (c - NXI)] : D22[r * NSTATES + (c - 640)]);
}

// ---------------- tanh forward-substitution scan ----------------
// eps[b,i] = tanh( (pre[b,i] + sum_{j<i} eps[b,j]*D11[i,j]) / Lam[i] )
__global__ __launch_bounds__(64) void eps_kernel() {
    __shared__ float es[128 * 64];
    __shared__ float li[128];
    int tid = threadIdx.x;
    size_t b = (size_t)blockIdx.x * 64 + tid;
    for (int i = tid; i < 128; i += 64) li[i] = g_LamInv[i];
    __syncthreads();
    for (int i = 0; i < 128; ++i) {
        float v = g_pre[b * 128 + i];
        const float* __restrict__ dr = &g_D11[i * 128];
        float v0 = 0.f, v1 = 0.f, v2 = 0.f, v3 = 0.f;
        int j = 0;
        for (; j + 3 < i; j += 4) {
            v0 = fmaf(es[(j + 0) * 64 + tid], dr[j + 0], v0);
            v1 = fmaf(es[(j + 1) * 64 + tid], dr[j + 1], v1);
            v2 = fmaf(es[(j + 2) * 64 + tid], dr[j + 2], v2);
            v3 = fmaf(es[(j + 3) * 64 + tid], dr[j + 3], v3);
        }
        for (; j < i; ++j) v0 = fmaf(es[j * 64 + tid], dr[j], v0);
        v += (v0 + v1) + (v2 + v3);
        float e = tanhf(v * li[i]);
        es[i * 64 + tid] = e;
        g_eps[b * 128 + i] = e;
    }
}

// ---------------- launch ----------------
extern "C" void kernel_launch(void* const* d_in, const int* in_sizes, int n_in,
                              void* d_out, int out_size) {
    (void)in_sizes; (void)n_in; (void)out_size;
    const float* w   = (const float*)d_in[1];
    const float* xi  = (const float*)d_in[2];
    const float* X   = (const float*)d_in[3];
    const float* Y   = (const float*)d_in[4];
    const float* B2  = (const float*)d_in[5];
    const float* C2  = (const float*)d_in[6];
    const float* D21 = (const float*)d_in[7];
    const float* D22 = (const float*)d_in[8];
    const float* D12 = (const float*)d_in[9];
    float* out   = (float*)d_out;
    float* out_u = out;                                 // (B,1,64)
    float* out_x = out + (size_t)BATCHN * NIN;          // (B,1,512)

    float *pH, *pM, *pZa, *pZb, *pT, *pR, *pWout, *pWpre, *pPre, *pEps;
    cudaGetSymbolAddress((void**)&pH, g_H);
    cudaGetSymbolAddress((void**)&pM, g_M);
    cudaGetSymbolAddress((void**)&pZa, g_Za);
    cudaGetSymbolAddress((void**)&pZb, g_Zb);
    cudaGetSymbolAddress((void**)&pT, g_T);
    cudaGetSymbolAddress((void**)&pR, g_R);
    cudaGetSymbolAddress((void**)&pWout, g_Wout);
    cudaGetSymbolAddress((void**)&pWpre, g_Wpre);
    cudaGetSymbolAddress((void**)&pPre, g_pre);
    cudaGetSymbolAddress((void**)&pEps, g_eps);

    // 0) H = X^T X + eps*I
    gemm64<true, false><<<dim3(HDIM / 64, HDIM / 64), 256>>>(
        X, X, pH, HDIM, HDIM, HDIM, HDIM, HDIM, HDIM, nullptr, 2);

    // 1-4) derived params needed by the pre-GEMM/scan
    diag_kernel<<<2, 256>>>();
    build_MZ<<<(NXI * NXI + 255) / 256, 256>>>(Y);
    build_Wpre<<<(LDIM * 640 + 255) / 256, 256>>>(D12);
    build_D11<<<(LDIM * LDIM + 255) / 256, 256>>>();

    // 5) pre = [xi|w] @ Wpre^T   (M=32768, N=128, K=640)   <-- ncu -s 5 lands here
    gemm_batch128<<<dim3(1, BATCHN / 128), 256>>>(
        xi, w, w, NXI, 640, 640, pWpre, 128, pPre, nullptr, 0);

    // 6) tanh forward substitution
    eps_kernel<<<BATCHN / 64, 64>>>();

    // 7-8) remaining builders
    build_R<<<(NXI * 768 + 255) / 256, 256>>>(B2);
    build_WoutTop<<<(NIN * 768 + 255) / 256, 256>>>(C2, D21, D22);

    // 9..) Newton-Schulz on M = D^-1 E, Z0 = ALPHA*I (Z1 prebuilt in build_MZ)
    float* Zc = pZa;
    float* Zn = pZb;
    for (int it = 0; it < NEWTON_ITERS; ++it) {
        gemm64<false, false><<<dim3(8, 8), 256>>>(
            pM, Zc, pT, NXI, NXI, NXI, NXI, NXI, NXI, nullptr, 0);
        gemm64<false, false><<<dim3(8, 8), 256>>>(
            Zc, pT, Zn, NXI, NXI, NXI, NXI, NXI, NXI, Zc, 1);
        float* tmp = Zc; Zc = Zn; Zn = tmp;
    }

    // Wout rows 64..575 = Minv @ (D^-1 [Fm|B1|B2]) = Einv @ [Fm|B1|B2]
    gemm64<false, false><<<dim3(768 / 64, NXI / 64), 256>>>(
        Zc, pR, pWout + 64 * 768, NXI, 768, NXI, NXI, 768, 768, nullptr, 0);

    // [u | xi_] = [xi|eps|w] @ Wout^T   (M=32768, N=576(pad 640), K=768)
    gemm_batch128<<<dim3(5, BATCHN / 128), 256>>>(
        xi, pEps, w, NXI, 640, 768, pWout, 576, out_u, out_x, 1);
}

// round 5
// speedup vs baseline: 1.7547x; 1.3915x over previous
#include <cuda_runtime.h>
#include <cuda_bf16.h>
#include <math.h>
#include <stdint.h>

#define NXI 512
#define LDIM 128
#define NSTATES 128
#define NIN 64
#define HDIM 1152           // 2*NXI + LDIM
#define BATCHN 32768
#define EPSV 0.001f
#define ALPHA 0.55f
#define NEWTON_ITERS 9      // + fused first step = 10 squarings

// ---------------- device scratch ----------------
__device__ float g_H[HDIM * HDIM];
__device__ float g_M[NXI * NXI];
__device__ float g_Za[NXI * NXI];
__device__ float g_Zb[NXI * NXI];
__device__ float g_T[NXI * NXI];
__device__ float g_R[NXI * 768];
__device__ float g_Wout[640 * 768];       // fp32; rows 576..639 stay zero (never written)
__device__ float g_D11[LDIM * LDIM];
__device__ float g_LamInv[LDIM];
__device__ float g_dinv[NXI];
__device__ float g_pre[(size_t)BATCHN * LDIM];

// split-bf16 operands for tensor-core GEMMs
__device__ __nv_bfloat16 g_AH[(size_t)BATCHN * 768];   // [xi | eps | w]
__device__ __nv_bfloat16 g_AL[(size_t)BATCHN * 768];
__device__ __nv_bfloat16 g_WpreH[LDIM * 768];          // cols 0..511 = -H21, 640..767 = D12
__device__ __nv_bfloat16 g_WpreL[LDIM * 768];
__device__ __nv_bfloat16 g_WoutH[640 * 768];
__device__ __nv_bfloat16 g_WoutL[640 * 768];

// ---------------- PTX helpers ----------------
__device__ __forceinline__ uint32_t smem_u32(const void* p) {
    uint32_t a;
    asm("{ .reg .u64 t; cvta.to.shared.u64 t, %1; cvt.u32.u64 %0, t; }" : "=r"(a) : "l"(p));
    return a;
}
#define LDSM4(r0, r1, r2, r3, addr) \
    asm volatile("ldmatrix.sync.aligned.m8n8.x4.shared.b16 {%0,%1,%2,%3}, [%4];" \
                 : "=r"(r0), "=r"(r1), "=r"(r2), "=r"(r3) : "r"(addr))
#define MMA16816(d, a, b0, b1) \
    asm volatile("mma.sync.aligned.m16n8k16.row.col.f32.bf16.bf16.f32 " \
                 "{%0,%1,%2,%3},{%4,%5,%6,%7},{%8,%9},{%0,%1,%2,%3};" \
                 : "+f"(d[0]), "+f"(d[1]), "+f"(d[2]), "+f"(d[3]) \
                 : "r"(a[0]), "r"(a[1]), "r"(a[2]), "r"(a[3]), "r"(b0), "r"(b1))

// ============ warp-mma split-bf16 GEMM: out tile(128x128) = A * W^T ============
// A: (M x lda) bf16 hi/lo rows m0..+127; W: (N x ldb) bf16 hi/lo rows n0..+127.
// k-chunks of 32 with skip remap (to jump over eps columns for the pre-GEMM).
#define BK 32
#define LDS (BK + 8)     // 40 bf16 = 80B row stride: conflict-free ldmatrix
__global__ __launch_bounds__(256) void mma_gemm(
    const __nv_bfloat16* __restrict__ Ah, const __nv_bfloat16* __restrict__ Al,
    const __nv_bfloat16* __restrict__ Bh, const __nv_bfloat16* __restrict__ Bl,
    int nchunks, int skip_at, int skip_amt, int lda, int ldb,
    float* __restrict__ out0, float* __restrict__ out1, int mode) {
    __shared__ __nv_bfloat16 sAh[128 * LDS], sAl[128 * LDS];
    __shared__ __nv_bfloat16 sBh[128 * LDS], sBl[128 * LDS];
    const int tid = threadIdx.x;
    const int wid = tid >> 5, lane = tid & 31;
    const size_t m0 = (size_t)blockIdx.y * 128;
    const int n0 = blockIdx.x * 128;
    const int wm = (wid & 3) * 32;     // warp m offset in tile
    const int wn = (wid >> 2) * 64;    // warp n offset in tile

    float acc[2][8][4] = {};

    const int lr = tid >> 1;           // load row 0..127
    const int lc = (tid & 1) * 16;     // load col 0 / 16

    const uint32_t uAh = smem_u32(sAh), uAl = smem_u32(sAl);
    const uint32_t uBh = smem_u32(sBh), uBl = smem_u32(sBl);
    // ldmatrix lane offsets
    const int am = wm + (lane & 15);
    const int ak = (lane >> 4) * 8;
    const int bn = wn + (lane & 7) + (lane >> 4) * 8;
    const int bk = ((lane >> 3) & 1) * 8;

    uint4 pa[2][2], pb[2][2];
    auto gload = [&](int c) {
        const int kc = c * BK;
        const int col = (kc >= skip_at) ? kc + skip_amt : kc;
        const size_t oa = (m0 + lr) * (size_t)lda + col + lc;
        const size_t ob = (size_t)(n0 + lr) * ldb + col + lc;
        pa[0][0] = *(const uint4*)(Ah + oa); pa[0][1] = *(const uint4*)(Ah + oa + 8);
        pa[1][0] = *(const uint4*)(Al + oa); pa[1][1] = *(const uint4*)(Al + oa + 8);
        pb[0][0] = *(const uint4*)(Bh + ob); pb[0][1] = *(const uint4*)(Bh + ob + 8);
        pb[1][0] = *(const uint4*)(Bl + ob); pb[1][1] = *(const uint4*)(Bl + ob + 8);
    };

    gload(0);
    for (int c = 0; c < nchunks; ++c) {
        const int so = lr * LDS + lc;
        *(uint4*)(sAh + so) = pa[0][0]; *(uint4*)(sAh + so + 8) = pa[0][1];
        *(uint4*)(sAl + so) = pa[1][0]; *(uint4*)(sAl + so + 8) = pa[1][1];
        *(uint4*)(sBh + so) = pb[0][0]; *(uint4*)(sBh + so + 8) = pb[0][1];
        *(uint4*)(sBl + so) = pb[1][0]; *(uint4*)(sBl + so + 8) = pb[1][1];
        __syncthreads();
        if (c + 1 < nchunks) gload(c + 1);
#pragma unroll
        for (int k16 = 0; k16 < BK; k16 += 16) {
            uint32_t ahf[2][4], alf[2][4], bhf[4][4], blf[4][4];
#pragma unroll
            for (int mi = 0; mi < 2; ++mi) {
                const uint32_t off = (uint32_t)(((am + mi * 16) * LDS + ak + k16) * 2);
                LDSM4(ahf[mi][0], ahf[mi][1], ahf[mi][2], ahf[mi][3], uAh + off);
                LDSM4(alf[mi][0], alf[mi][1], alf[mi][2], alf[mi][3], uAl + off);
            }
#pragma unroll
            for (int j = 0; j < 4; ++j) {
                const uint32_t off = (uint32_t)(((bn + j * 16) * LDS + bk + k16) * 2);
                LDSM4(bhf[j][0], bhf[j][1], bhf[j][2], bhf[j][3], uBh + off);
                LDSM4(blf[j][0], blf[j][1], blf[j][2], blf[j][3], uBl + off);
            }
#pragma unroll
            for (int mi = 0; mi < 2; ++mi)
#pragma unroll
                for (int j = 0; j < 4; ++j)
#pragma unroll
                    for (int h = 0; h < 2; ++h) {
                        float* d = acc[mi][j * 2 + h];
                        MMA16816(d, ahf[mi], bhf[j][h * 2], bhf[j][h * 2 + 1]);
                        MMA16816(d, ahf[mi], blf[j][h * 2], blf[j][h * 2 + 1]);
                        MMA16816(d, alf[mi], bhf[j][h * 2], bhf[j][h * 2 + 1]);
                    }
        }
        __syncthreads();
    }

    // epilogue: acc[mi][j] is m16n8 frag at (wm+mi*16, wn+j*8)
    const int rrow = lane >> 2;
    const int rcol = (lane & 3) * 2;
#pragma unroll
    for (int mi = 0; mi < 2; ++mi) {
#pragma unroll
        for (int j = 0; j < 8; ++j) {
            const float* d = acc[mi][j];
            const int n = n0 + wn + j * 8 + rcol;
#pragma unroll
            for (int half = 0; half < 2; ++half) {
                const size_t m = m0 + wm + mi * 16 + rrow + half * 8;
                const float v0 = d[half * 2 + 0], v1 = d[half * 2 + 1];
                if (mode == 0) {
                    float2* dst = (float2*)(out0 + m * 128 + n);
                    *dst = make_float2(v0, v1);
                } else {
                    if (n < NIN) *(float2*)(out0 + m * NIN + n) = make_float2(v0, v1);
                    else if (n < 576) *(float2*)(out1 + m * NXI + (n - NIN)) = make_float2(v0, v1);
                }
            }
        }
    }
}

// ---------------- generic small GEMM (fp32, Newton / H) ----------------
template <bool TA, bool TB>
__global__ __launch_bounds__(256) void gemm64(const float* __restrict__ A,
                                              const float* __restrict__ B,
                                              float* __restrict__ C,
                                              int M, int N, int K,
                                              int lda, int ldb, int ldc,
                                              const float* __restrict__ D, int emode) {
    __shared__ float As[16][65];
    __shared__ float Bs[16][65];
    int tid = threadIdx.x;
    int tx = tid & 15, ty = tid >> 4;
    int m0 = blockIdx.y * 64, n0 = blockIdx.x * 64;
    float acc[4][4] = {};
    for (int k0 = 0; k0 < K; k0 += 16) {
        __syncthreads();
#pragma unroll
        for (int rr = 0; rr < 4; ++rr) {
            int idx = tid + rr * 256;
            if (TA) { int k = idx >> 6, m = idx & 63; As[k][m] = A[(size_t)(k0 + k) * lda + m0 + m]; }
            else    { int m = idx >> 4, k = idx & 15; As[k][m] = A[(size_t)(m0 + m) * lda + k0 + k]; }
            if (TB) { int n = idx >> 4, k = idx & 15; Bs[k][n] = B[(size_t)(n0 + n) * ldb + k0 + k]; }
            else    { int k = idx >> 6, n = idx & 63; Bs[k][n] = B[(size_t)(k0 + k) * ldb + n0 + n]; }
        }
        __syncthreads();
#pragma unroll
        for (int k = 0; k < 16; ++k) {
            float av[4], bv[4];
#pragma unroll
            for (int i = 0; i < 4; ++i) av[i] = As[k][ty * 4 + i];
#pragma unroll
            for (int j = 0; j < 4; ++j) bv[j] = Bs[k][tx * 4 + j];
#pragma unroll
            for (int i = 0; i < 4; ++i)
#pragma unroll
                for (int j = 0; j < 4; ++j) acc[i][j] = fmaf(av[i], bv[j], acc[i][j]);
        }
    }
#pragma unroll
    for (int i = 0; i < 4; ++i) {
        int m = m0 + ty * 4 + i;
#pragma unroll
        for (int j = 0; j < 4; ++j) {
            int n = n0 + tx * 4 + j;
            float v = acc[i][j];
            if (emode == 1) v = 2.0f * D[(size_t)m * ldc + n] - v;
            else if (emode == 2 && m == n) v += EPSV;
            C[(size_t)m * ldc + n] = v;
        }
    }
}

// ---------------- builders ----------------
__device__ __forceinline__ void split_store(__nv_bfloat16* H, __nv_bfloat16* L, size_t idx, float v) {
    __nv_bfloat16 h = __float2bfloat16(v);
    H[idx] = h;
    L[idx] = __float2bfloat16(v - __bfloat162float(h));
}
__global__ void diag_kernel() {
    int i = blockIdx.x * blockDim.x + threadIdx.x;
    if (i >= NXI) return;
    g_dinv[i] = 2.0f / (g_H[(size_t)i * HDIM + i] + g_H[(size_t)(640 + i) * HDIM + 640 + i]);
}
__global__ void build_MZ(const float* __restrict__ Y) {
    int idx = blockIdx.x * blockDim.x + threadIdx.x;
    if (idx >= NXI * NXI) return;
    int i = idx >> 9, j = idx & 511;
    float e = 0.5f * (g_H[(size_t)i * HDIM + j] + g_H[(size_t)(640 + i) * HDIM + 640 + j] +
                      Y[(size_t)i * NXI + j] - Y[(size_t)j * NXI + i]);
    float m = g_dinv[i] * e;
    g_M[idx] = m;
    g_Za[idx] = ((i == j) ? 2.0f * ALPHA : 0.0f) - ALPHA * ALPHA * m;
}
__global__ void build_WpreSplit(const float* __restrict__ D12) {
    int idx = blockIdx.x * blockDim.x + threadIdx.x;
    if (idx >= LDIM * 640) return;
    int rr = idx / 640, c = idx - rr * 640;
    float v = (c < NXI) ? -g_H[(size_t)(NXI + rr) * HDIM + c] : D12[rr * NSTATES + (c - NXI)];
    int dc = (c < NXI) ? c : c + 128;
    split_store(g_WpreH, g_WpreL, (size_t)rr * 768 + dc, v);
}
__global__ void build_D11() {
    int idx = blockIdx.x * blockDim.x + threadIdx.x;
    if (idx >= LDIM * LDIM) return;
    int i = idx >> 7, j = idx & 127;
    g_D11[idx] = (j < i) ? -g_H[(size_t)(NXI + i) * HDIM + NXI + j] : 0.0f;
    if (j == i) g_LamInv[i] = 2.0f / g_H[(size_t)(NXI + i) * HDIM + NXI + i];
}
__global__ void build_R(const float* __restrict__ B2) {
    int idx = blockIdx.x * blockDim.x + threadIdx.x;
    if (idx >= NXI * 768) return;
    int i = idx / 768, c = idx - i * 768;
    float v = (c < 640) ? g_H[(size_t)(640 + i) * HDIM + c] : B2[i * NSTATES + (c - 640)];
    g_R[idx] = g_dinv[i] * v;
}
__global__ void build_WoutTop(const float* __restrict__ C2, const float* __restrict__ D21,
                              const float* __restrict__ D22) {
    int idx = blockIdx.x * blockDim.x + threadIdx.x;
    if (idx >= NIN * 768) return;
    int rr = idx / 768, c = idx - rr * 768;
    g_Wout[idx] = (c < NXI) ? C2[rr * NXI + c]
                            : (c < 640 ? D21[rr * LDIM + (c - NXI)] : D22[rr * NSTATES + (c - 640)]);
}
__global__ void conv_Wout() {
    int idx = blockIdx.x * blockDim.x + threadIdx.x;
    if (idx >= 640 * 768) return;
    split_store(g_WoutH, g_WoutL, idx, g_Wout[idx]);
}
// convert xi (cols 0..511) and w (-> cols 640..767) into g_AH/g_AL rows
__global__ void conv_A(const float* __restrict__ xi, const float* __restrict__ w) {
    size_t b = blockIdx.y;
    int c0 = (blockIdx.x * blockDim.x + threadIdx.x) * 4;
    if (c0 >= 640) return;
    float4 v;
    int dc;
    if (c0 < NXI) { v = *(const float4*)(xi + b * NXI + c0); dc = c0; }
    else          { v = *(const float4*)(w + b * NSTATES + (c0 - NXI)); dc = c0 + 128; }
    size_t o = b * 768 + dc;
    split_store(g_AH, g_AL, o + 0, v.x);
    split_store(g_AH, g_AL, o + 1, v.y);
    split_store(g_AH, g_AL, o + 2, v.z);
    split_store(g_AH, g_AL, o + 3, v.w);
}

// ---------------- tanh forward-substitution scan ----------------
__global__ __launch_bounds__(64) void eps_kernel() {
    __shared__ float es[128 * 64];
    __shared__ float li[128];
    int tid = threadIdx.x;
    size_t b = (size_t)blockIdx.x * 64 + tid;
    for (int i = tid; i < 128; i += 64) li[i] = g_LamInv[i];
    __syncthreads();
    for (int i = 0; i < 128; ++i) {
        float v = g_pre[b * 128 + i];
        const float* __restrict__ dr = &g_D11[i * 128];
        float v0 = 0.f, v1 = 0.f, v2 = 0.f, v3 = 0.f;
        int j = 0;
        for (; j + 3 < i; j += 4) {
            v0 = fmaf(es[(j + 0) * 64 + tid], dr[j + 0], v0);
            v1 = fmaf(es[(j + 1) * 64 + tid], dr[j + 1], v1);
            v2 = fmaf(es[(j + 2) * 64 + tid], dr[j + 2], v2);
            v3 = fmaf(es[(j + 3) * 64 + tid], dr[j + 3], v3);
        }
        for (; j < i; ++j) v0 = fmaf(es[j * 64 + tid], dr[j], v0);
        v += (v0 + v1) + (v2 + v3);
        es[i * 64 + tid] = tanhf(v * li[i]);
    }
    for (int i = 0; i < 128; ++i) {
        split_store(g_AH, g_AL, b * 768 + 512 + i, es[i * 64 + tid]);
    }
}

// ---------------- launch ----------------
extern "C" void kernel_launch(void* const* d_in, const int* in_sizes, int n_in,
                              void* d_out, int out_size) {
    (void)in_sizes; (void)n_in; (void)out_size;
    const float* w   = (const float*)d_in[1];
    const float* xi  = (const float*)d_in[2];
    const float* X   = (const float*)d_in[3];
    const float* Y   = (const float*)d_in[4];
    const float* B2  = (const float*)d_in[5];
    const float* C2  = (const float*)d_in[6];
    const float* D21 = (const float*)d_in[7];
    const float* D22 = (const float*)d_in[8];
    const float* D12 = (const float*)d_in[9];
    float* out   = (float*)d_out;
    float* out_u = out;                                 // (B,1,64)
    float* out_x = out + (size_t)BATCHN * NIN;          // (B,1,512)

    float *pH, *pM, *pZa, *pZb, *pT, *pR, *pWout, *pPre;
    __nv_bfloat16 *pAH, *pAL, *pWpreH, *pWpreL, *pWoutH, *pWoutL;
    cudaGetSymbolAddress((void**)&pH, g_H);
    cudaGetSymbolAddress((void**)&pM, g_M);
    cudaGetSymbolAddress((void**)&pZa, g_Za);
    cudaGetSymbolAddress((void**)&pZb, g_Zb);
    cudaGetSymbolAddress((void**)&pT, g_T);
    cudaGetSymbolAddress((void**)&pR, g_R);
    cudaGetSymbolAddress((void**)&pWout, g_Wout);
    cudaGetSymbolAddress((void**)&pPre, g_pre);
    cudaGetSymbolAddress((void**)&pAH, g_AH);
    cudaGetSymbolAddress((void**)&pAL, g_AL);
    cudaGetSymbolAddress((void**)&pWpreH, g_WpreH);
    cudaGetSymbolAddress((void**)&pWpreL, g_WpreL);
    cudaGetSymbolAddress((void**)&pWoutH, g_WoutH);
    cudaGetSymbolAddress((void**)&pWoutL, g_WoutL);

    // 0) H = X^T X + eps*I
    gemm64<true, false><<<dim3(HDIM / 64, HDIM / 64), 256>>>(
        X, X, pH, HDIM, HDIM, HDIM, HDIM, HDIM, HDIM, nullptr, 2);

    // builders needed by pre-GEMM / scan
    diag_kernel<<<2, 256>>>();
    build_MZ<<<(NXI * NXI + 255) / 256, 256>>>(Y);
    build_WpreSplit<<<(LDIM * 640 + 255) / 256, 256>>>(D12);
    build_D11<<<(LDIM * LDIM + 255) / 256, 256>>>();
    conv_A<<<dim3(1, BATCHN), 160>>>(xi, w);

    // pre = [xi|w] @ Wpre^T (tensor mma, split-bf16): K=640, skip eps cols
    mma_gemm<<<dim3(1, BATCHN / 128), 256>>>(
        pAH, pAL, pWpreH, pWpreL, 20, 512, 128, 768, 768, pPre, nullptr, 0);

    // tanh forward substitution (writes eps cols of A, split-bf16)
    eps_kernel<<<BATCHN / 64, 64>>>();

    // remaining builders
    build_R<<<(NXI * 768 + 255) / 256, 256>>>(B2);
    build_WoutTop<<<(NIN * 768 + 255) / 256, 256>>>(C2, D21, D22);

    // Newton-Schulz on M = D^-1 E (Z1 prebuilt in build_MZ)
    float* Zc = pZa;
    float* Zn = pZb;
    for (int it = 0; it < NEWTON_ITERS; ++it) {
        gemm64<false, false><<<dim3(8, 8), 256>>>(
            pM, Zc, pT, NXI, NXI, NXI, NXI, NXI, NXI, nullptr, 0);
        gemm64<false, false><<<dim3(8, 8), 256>>>(
            Zc, pT, Zn, NXI, NXI, NXI, NXI, NXI, NXI, Zc, 1);
        float* tmp = Zc; Zc = Zn; Zn = tmp;
    }

    // Wout rows 64..575 = Minv @ (D^-1 [Fm|B1|B2]) = Einv @ [Fm|B1|B2]
    gemm64<false, false><<<dim3(768 / 64, NXI / 64), 256>>>(
        Zc, pR, pWout + 64 * 768, NXI, 768, NXI, NXI, 768, 768, nullptr, 0);
    conv_Wout<<<(640 * 768 + 255) / 256, 256>>>();

    // [u | xi_] = [xi|eps|w] @ Wout^T (tensor mma, split-bf16): K=768, N=640 (576 real)
    mma_gemm<<<dim3(5, BATCHN / 128), 256>>>(
        pAH, pAL, pWoutH, pWoutL, 24, 1 << 30, 0, 768, 768, out_u, out_x, 1);
}

// round 6
// speedup vs baseline: 2.9295x; 1.6696x over previous
#include <cuda_runtime.h>
#include <cuda_bf16.h>
#include <math.h>
#include <stdint.h>

#define NXI 512
#define LDIM 128
#define NSTATES 128
#define NIN 64
#define HDIM 1152           // 2*NXI + LDIM
#define BATCHN 32768
#define EPSV 0.001f
#define ALPHA 0.55f
#define NEWTON_ITERS 9      // + fused first step = 10 squarings

// ---------------- device scratch ----------------
__device__ float g_H[HDIM * HDIM];
__device__ float g_Zf[2][NXI * NXI];
__device__ float g_Wout[640 * 768];       // rows 576..639 stay zero (never written)
__device__ float g_D11[LDIM * LDIM];
__device__ float g_LamInv[LDIM];
__device__ float g_dinv[NXI];
__device__ float g_pre[(size_t)BATCHN * LDIM];

// split-bf16 operand arrays
__device__ __nv_bfloat16 g_AH[(size_t)BATCHN * 768];   // [xi | eps | w]
__device__ __nv_bfloat16 g_AL[(size_t)BATCHN * 768];
__device__ __nv_bfloat16 g_WpreH[LDIM * 768];
__device__ __nv_bfloat16 g_WpreL[LDIM * 768];
__device__ __nv_bfloat16 g_WoutH[640 * 768];
__device__ __nv_bfloat16 g_WoutL[640 * 768];
__device__ __nv_bfloat16 g_XtH[HDIM * HDIM];           // X transposed, split
__device__ __nv_bfloat16 g_XtL[HDIM * HDIM];
__device__ __nv_bfloat16 g_MH[NXI * NXI], g_ML[NXI * NXI];
__device__ __nv_bfloat16 g_ZH[2][NXI * NXI], g_ZL[2][NXI * NXI];
__device__ __nv_bfloat16 g_ZTH[2][NXI * NXI], g_ZTL[2][NXI * NXI];
__device__ __nv_bfloat16 g_TtH[NXI * NXI], g_TtL[NXI * NXI];
__device__ __nv_bfloat16 g_RtH[768 * NXI], g_RtL[768 * NXI];

// ---------------- PTX helpers ----------------
__device__ __forceinline__ uint32_t smem_u32(const void* p) {
    uint32_t a;
    asm("{ .reg .u64 t; cvta.to.shared.u64 t, %1; cvt.u32.u64 %0, t; }" : "=r"(a) : "l"(p));
    return a;
}
#define LDSM4(r0, r1, r2, r3, addr) \
    asm volatile("ldmatrix.sync.aligned.m8n8.x4.shared.b16 {%0,%1,%2,%3}, [%4];" \
                 : "=r"(r0), "=r"(r1), "=r"(r2), "=r"(r3) : "r"(addr))
#define MMA16816(d, a, b0, b1) \
    asm volatile("mma.sync.aligned.m16n8k16.row.col.f32.bf16.bf16.f32 " \
                 "{%0,%1,%2,%3},{%4,%5,%6,%7},{%8,%9},{%0,%1,%2,%3};" \
                 : "+f"(d[0]), "+f"(d[1]), "+f"(d[2]), "+f"(d[3]) \
                 : "r"(a[0]), "r"(a[1]), "r"(a[2]), "r"(a[3]), "r"(b0), "r"(b1))

__device__ __forceinline__ void split_store(__nv_bfloat16* H, __nv_bfloat16* L, size_t idx, float v) {
    __nv_bfloat16 h = __float2bfloat16(v);
    H[idx] = h;
    L[idx] = __float2bfloat16(v - __bfloat162float(h));
}

// ============ big batch GEMM (128x128 tiles, 256 thr): out = A * W^T ============
#define BK 32
#define LDSW (BK + 8)
__global__ __launch_bounds__(256) void mma_gemm(
    const __nv_bfloat16* __restrict__ Ah, const __nv_bfloat16* __restrict__ Al,
    const __nv_bfloat16* __restrict__ Bh, const __nv_bfloat16* __restrict__ Bl,
    int nchunks, int skip_at, int skip_amt, int lda, int ldb,
    float* __restrict__ out0, float* __restrict__ out1, int mode) {
    __shared__ __nv_bfloat16 sAh[128 * LDSW], sAl[128 * LDSW];
    __shared__ __nv_bfloat16 sBh[128 * LDSW], sBl[128 * LDSW];
    const int tid = threadIdx.x;
    const int wid = tid >> 5, lane = tid & 31;
    const size_t m0 = (size_t)blockIdx.y * 128;
    const int n0 = blockIdx.x * 128;
    const int wm = (wid & 3) * 32;
    const int wn = (wid >> 2) * 64;

    float acc[2][8][4] = {};
    const int lr = tid >> 1;
    const int lc = (tid & 1) * 16;
    const uint32_t uAh = smem_u32(sAh), uAl = smem_u32(sAl);
    const uint32_t uBh = smem_u32(sBh), uBl = smem_u32(sBl);
    const int am = wm + (lane & 15);
    const int ak = (lane >> 4) * 8;
    const int bn = wn + (lane & 7) + (lane >> 4) * 8;
    const int bk = ((lane >> 3) & 1) * 8;

    uint4 pa[2][2], pb[2][2];
    auto gload = [&](int c) {
        const int kc = c * BK;
        const int col = (kc >= skip_at) ? kc + skip_amt : kc;
        const size_t oa = (m0 + lr) * (size_t)lda + col + lc;
        const size_t ob = (size_t)(n0 + lr) * ldb + col + lc;
        pa[0][0] = *(const uint4*)(Ah + oa); pa[0][1] = *(const uint4*)(Ah + oa + 8);
        pa[1][0] = *(const uint4*)(Al + oa); pa[1][1] = *(const uint4*)(Al + oa + 8);
        pb[0][0] = *(const uint4*)(Bh + ob); pb[0][1] = *(const uint4*)(Bh + ob + 8);
        pb[1][0] = *(const uint4*)(Bl + ob); pb[1][1] = *(const uint4*)(Bl + ob + 8);
    };

    gload(0);
    for (int c = 0; c < nchunks; ++c) {
        const int so = lr * LDSW + lc;
        *(uint4*)(sAh + so) = pa[0][0]; *(uint4*)(sAh + so + 8) = pa[0][1];
        *(uint4*)(sAl + so) = pa[1][0]; *(uint4*)(sAl + so + 8) = pa[1][1];
        *(uint4*)(sBh + so) = pb[0][0]; *(uint4*)(sBh + so + 8) = pb[0][1];
        *(uint4*)(sBl + so) = pb[1][0]; *(uint4*)(sBl + so + 8) = pb[1][1];
        __syncthreads();
        if (c + 1 < nchunks) gload(c + 1);
#pragma unroll
        for (int k16 = 0; k16 < BK; k16 += 16) {
            uint32_t ahf[2][4], alf[2][4], bhf[4][4], blf[4][4];
#pragma unroll
            for (int mi = 0; mi < 2; ++mi) {
                const uint32_t off = (uint32_t)(((am + mi * 16) * LDSW + ak + k16) * 2);
                LDSM4(ahf[mi][0], ahf[mi][1], ahf[mi][2], ahf[mi][3], uAh + off);
                LDSM4(alf[mi][0], alf[mi][1], alf[mi][2], alf[mi][3], uAl + off);
            }
#pragma unroll
            for (int j = 0; j < 4; ++j) {
                const uint32_t off = (uint32_t)(((bn + j * 16) * LDSW + bk + k16) * 2);
                LDSM4(bhf[j][0], bhf[j][1], bhf[j][2], bhf[j][3], uBh + off);
                LDSM4(blf[j][0], blf[j][1], blf[j][2], blf[j][3], uBl + off);
            }
#pragma unroll
            for (int mi = 0; mi < 2; ++mi)
#pragma unroll
                for (int j = 0; j < 4; ++j)
#pragma unroll
                    for (int h = 0; h < 2; ++h) {
                        float* d = acc[mi][j * 2 + h];
                        MMA16816(d, ahf[mi], bhf[j][h * 2], bhf[j][h * 2 + 1]);
                        MMA16816(d, ahf[mi], blf[j][h * 2], blf[j][h * 2 + 1]);
                        MMA16816(d, alf[mi], bhf[j][h * 2], bhf[j][h * 2 + 1]);
                    }
        }
        __syncthreads();
    }
    const int rrow = lane >> 2;
    const int rcol = (lane & 3) * 2;
#pragma unroll
    for (int mi = 0; mi < 2; ++mi)
#pragma unroll
        for (int j = 0; j < 8; ++j) {
            const float* d = acc[mi][j];
            const int n = n0 + wn + j * 8 + rcol;
#pragma unroll
            for (int half = 0; half < 2; ++half) {
                const size_t m = m0 + wm + mi * 16 + rrow + half * 8;
                const float v0 = d[half * 2 + 0], v1 = d[half * 2 + 1];
                if (mode == 0) {
                    *(float2*)(out0 + m * 128 + n) = make_float2(v0, v1);
                } else {
                    if (n < NIN) *(float2*)(out0 + m * NIN + n) = make_float2(v0, v1);
                    else if (n < 576) *(float2*)(out1 + m * NXI + (n - NIN)) = make_float2(v0, v1);
                }
            }
        }
}

// ============ small tensor GEMM (64x64 tiles, 128 thr): C = A * B^T ============
// emode: 0 = H (+eps diag, fp32 out) ; 1 = T (write transposed splits only)
//        2 = Newton Zn = 2*zin - C (fp32 out + row splits + transposed splits)
//        3 = plain fp32 out
#define LDS2 (BK + 8)
__global__ __launch_bounds__(128) void tc2(
    const __nv_bfloat16* __restrict__ Ah, const __nv_bfloat16* __restrict__ Al,
    const __nv_bfloat16* __restrict__ Bh, const __nv_bfloat16* __restrict__ Bl,
    int K, int lda, int ldb,
    float* __restrict__ outf, int ldc,
    __nv_bfloat16* __restrict__ oH, __nv_bfloat16* __restrict__ oL,
    __nv_bfloat16* __restrict__ oTH, __nv_bfloat16* __restrict__ oTL,
    const float* __restrict__ zin, int emode) {
    __shared__ __nv_bfloat16 sAh[64 * LDS2], sAl[64 * LDS2];
    __shared__ __nv_bfloat16 sBh[64 * LDS2], sBl[64 * LDS2];
    const int tid = threadIdx.x;
    const int wid = tid >> 5, lane = tid & 31;
    const int m0 = blockIdx.y * 64;
    const int n0 = blockIdx.x * 64;
    const int wm = (wid & 1) * 32;
    const int wn = (wid >> 1) * 32;

    float acc[2][4][4] = {};
    const int lr = tid >> 1;
    const int lc = (tid & 1) * 16;
    const uint32_t uAh = smem_u32(sAh), uAl = smem_u32(sAl);
    const uint32_t uBh = smem_u32(sBh), uBl = smem_u32(sBl);
    const int am = wm + (lane & 15);
    const int ak = (lane >> 4) * 8;
    const int bn = wn + (lane & 7) + (lane >> 4) * 8;
    const int bk = ((lane >> 3) & 1) * 8;

    uint4 pa[2][2], pb[2][2];
    auto gload = [&](int c) {
        const int col = c * BK;
        const size_t oa = (size_t)(m0 + lr) * lda + col + lc;
        const size_t ob = (size_t)(n0 + lr) * ldb + col + lc;
        pa[0][0] = *(const uint4*)(Ah + oa); pa[0][1] = *(const uint4*)(Ah + oa + 8);
        pa[1][0] = *(const uint4*)(Al + oa); pa[1][1] = *(const uint4*)(Al + oa + 8);
        pb[0][0] = *(const uint4*)(Bh + ob); pb[0][1] = *(const uint4*)(Bh + ob + 8);
        pb[1][0] = *(const uint4*)(Bl + ob); pb[1][1] = *(const uint4*)(Bl + ob + 8);
    };

    const int nchunks = K / BK;
    gload(0);
    for (int c = 0; c < nchunks; ++c) {
        const int so = lr * LDS2 + lc;
        *(uint4*)(sAh + so) = pa[0][0]; *(uint4*)(sAh + so + 8) = pa[0][1];
        *(uint4*)(sAl + so) = pa[1][0]; *(uint4*)(sAl + so + 8) = pa[1][1];
        *(uint4*)(sBh + so) = pb[0][0]; *(uint4*)(sBh + so + 8) = pb[0][1];
        *(uint4*)(sBl + so) = pb[1][0]; *(uint4*)(sBl + so + 8) = pb[1][1];
        __syncthreads();
        if (c + 1 < nchunks) gload(c + 1);
#pragma unroll
        for (int k16 = 0; k16 < BK; k16 += 16) {
            uint32_t ahf[2][4], alf[2][4], bhf[2][4], blf[2][4];
#pragma unroll
            for (int mi = 0; mi < 2; ++mi) {
                const uint32_t off = (uint32_t)(((am + mi * 16) * LDS2 + ak + k16) * 2);
                LDSM4(ahf[mi][0], ahf[mi][1], ahf[mi][2], ahf[mi][3], uAh + off);
                LDSM4(alf[mi][0], alf[mi][1], alf[mi][2], alf[mi][3], uAl + off);
            }
#pragma unroll
            for (int j = 0; j < 2; ++j) {
                const uint32_t off = (uint32_t)(((bn + j * 16) * LDS2 + bk + k16) * 2);
                LDSM4(bhf[j][0], bhf[j][1], bhf[j][2], bhf[j][3], uBh + off);
                LDSM4(blf[j][0], blf[j][1], blf[j][2], blf[j][3], uBl + off);
            }
#pragma unroll
            for (int mi = 0; mi < 2; ++mi)
#pragma unroll
                for (int j = 0; j < 2; ++j)
#pragma unroll
                    for (int h = 0; h < 2; ++h) {
                        float* d = acc[mi][j * 2 + h];
                        MMA16816(d, ahf[mi], bhf[j][h * 2], bhf[j][h * 2 + 1]);
                        MMA16816(d, ahf[mi], blf[j][h * 2], blf[j][h * 2 + 1]);
                        MMA16816(d, alf[mi], bhf[j][h * 2], bhf[j][h * 2 + 1]);
                    }
        }
        __syncthreads();
    }
    const int rrow = lane >> 2;
    const int rcol = (lane & 3) * 2;
#pragma unroll
    for (int mi = 0; mi < 2; ++mi)
#pragma unroll
        for (int j = 0; j < 4; ++j) {
            const float* d = acc[mi][j];
            const int n = n0 + wn + j * 8 + rcol;
#pragma unroll
            for (int half = 0; half < 2; ++half) {
                const int m = m0 + wm + mi * 16 + rrow + half * 8;
                float v0 = d[half * 2 + 0], v1 = d[half * 2 + 1];
                if (emode == 0) {
                    if (m == n) v0 += EPSV;
                    if (m == n + 1) v1 += EPSV;
                    *(float2*)(outf + (size_t)m * ldc + n) = make_float2(v0, v1);
                } else if (emode == 1) {
                    split_store(oTH, oTL, (size_t)n * NXI + m, v0);
                    split_store(oTH, oTL, (size_t)(n + 1) * NXI + m, v1);
                } else if (emode == 2) {
                    const size_t o = (size_t)m * NXI + n;
                    v0 = 2.0f * zin[o] - v0;
                    v1 = 2.0f * zin[o + 1] - v1;
                    *(float2*)(outf + o) = make_float2(v0, v1);
                    split_store(oH, oL, o, v0);
                    split_store(oH, oL, o + 1, v1);
                    split_store(oTH, oTL, (size_t)n * NXI + m, v0);
                    split_store(oTH, oTL, (size_t)(n + 1) * NXI + m, v1);
                } else {
                    *(float2*)(outf + (size_t)m * ldc + n) = make_float2(v0, v1);
                }
            }
        }
}

// ---------------- builders ----------------
// tiled split-transpose of X: Xt[i,k] = X[k,i]
__global__ void conv_Xt(const float* __restrict__ X) {
    __shared__ float t[32][33];
    const int bx = blockIdx.x * 32, by = blockIdx.y * 32;
    const int tx = threadIdx.x, ty = threadIdx.y;
#pragma unroll
    for (int r = 0; r < 32; r += 8)
        t[ty + r][tx] = X[(size_t)(by + ty + r) * HDIM + bx + tx];
    __syncthreads();
#pragma unroll
    for (int r = 0; r < 32; r += 8) {
        const float v = t[tx][ty + r];
        split_store(g_XtH, g_XtL, (size_t)(bx + ty + r) * HDIM + by + tx, v);
    }
}
__global__ void diag_kernel() {
    int i = blockIdx.x * blockDim.x + threadIdx.x;
    if (i >= NXI) return;
    g_dinv[i] = 2.0f / (g_H[(size_t)i * HDIM + i] + g_H[(size_t)(640 + i) * HDIM + 640 + i]);
}
// M = D^-1 E (splits); Z1 = 2a*I - a^2*M (fp32 + row splits + transposed splits)
__global__ void build_MZ(const float* __restrict__ Y) {
    int idx = blockIdx.x * blockDim.x + threadIdx.x;
    if (idx >= NXI * NXI) return;
    int i = idx >> 9, j = idx & 511;
    float e = 0.5f * (g_H[(size_t)i * HDIM + j] + g_H[(size_t)(640 + i) * HDIM + 640 + j] +
                      Y[(size_t)i * NXI + j] - Y[(size_t)j * NXI + i]);
    float m = g_dinv[i] * e;
    split_store(g_MH, g_ML, idx, m);
    float z = ((i == j) ? 2.0f * ALPHA : 0.0f) - ALPHA * ALPHA * m;
    g_Zf[0][idx] = z;
    split_store(g_ZH[0], g_ZL[0], idx, z);
    split_store(g_ZTH[0], g_ZTL[0], (size_t)j * NXI + i, z);
}
__global__ void build_WpreSplit(const float* __restrict__ D12) {
    int idx = blockIdx.x * blockDim.x + threadIdx.x;
    if (idx >= LDIM * 640) return;
    int rr = idx / 640, c = idx - rr * 640;
    float v = (c < NXI) ? -g_H[(size_t)(NXI + rr) * HDIM + c] : D12[rr * NSTATES + (c - NXI)];
    int dc = (c < NXI) ? c : c + 128;
    split_store(g_WpreH, g_WpreL, (size_t)rr * 768 + dc, v);
}
__global__ void build_D11() {
    int idx = blockIdx.x * blockDim.x + threadIdx.x;
    if (idx >= LDIM * LDIM) return;
    int i = idx >> 7, j = idx & 127;
    g_D11[idx] = (j < i) ? -g_H[(size_t)(NXI + i) * HDIM + NXI + j] : 0.0f;
    if (j == i) g_LamInv[i] = 2.0f / g_H[(size_t)(NXI + i) * HDIM + NXI + i];
}
// Rt[c, i] = dinv[i] * [Fm|B1|B2][i, c]  (transposed splits for tc2 B operand)
__global__ void build_Rt(const float* __restrict__ B2) {
    int idx = blockIdx.x * blockDim.x + threadIdx.x;
    if (idx >= NXI * 768) return;
    int i = idx / 768, c = idx - i * 768;
    float v = (c < 640) ? g_H[(size_t)(640 + i) * HDIM + c] : B2[i * NSTATES + (c - 640)];
    split_store(g_RtH, g_RtL, (size_t)c * NXI + i, g_dinv[i] * v);
}
__global__ void build_WoutTop(const float* __restrict__ C2, const float* __restrict__ D21,
                              const float* __restrict__ D22) {
    int idx = blockIdx.x * blockDim.x + threadIdx.x;
    if (idx >= NIN * 768) return;
    int rr = idx / 768, c = idx - rr * 768;
    g_Wout[idx] = (c < NXI) ? C2[rr * NXI + c]
                            : (c < 640 ? D21[rr * LDIM + (c - NXI)] : D22[rr * NSTATES + (c - 640)]);
}
__global__ void conv_Wout() {
    int idx = blockIdx.x * blockDim.x + threadIdx.x;
    if (idx >= 640 * 768) return;
    split_store(g_WoutH, g_WoutL, idx, g_Wout[idx]);
}
__global__ void conv_A(const float* __restrict__ xi, const float* __restrict__ w) {
    size_t idx = (size_t)blockIdx.x * blockDim.x + threadIdx.x;
    size_t b = idx / 160;
    int c0 = (int)(idx - b * 160) * 4;
    if (b >= BATCHN) return;
    float4 v;
    int dc;
    if (c0 < NXI) { v = *(const float4*)(xi + b * NXI + c0); dc = c0; }
    else          { v = *(const float4*)(w + b * NSTATES + (c0 - NXI)); dc = c0 + 128; }
    size_t o = b * 768 + dc;
    split_store(g_AH, g_AL, o + 0, v.x);
    split_store(g_AH, g_AL, o + 1, v.y);
    split_store(g_AH, g_AL, o + 2, v.z);
    split_store(g_AH, g_AL, o + 3, v.w);
}

// ---------------- tanh forward-substitution scan ----------------
__global__ __launch_bounds__(64) void eps_kernel() {
    __shared__ float es[128 * 64];
    __shared__ float li[128];
    int tid = threadIdx.x;
    size_t b = (size_t)blockIdx.x * 64 + tid;
    for (int i = tid; i < 128; i += 64) li[i] = g_LamInv[i];
    __syncthreads();
    for (int i = 0; i < 128; ++i) {
        float v = g_pre[b * 128 + i];
        const float* __restrict__ dr = &g_D11[i * 128];
        float v0 = 0.f, v1 = 0.f, v2 = 0.f, v3 = 0.f;
        int j = 0;
        for (; j + 3 < i; j += 4) {
            v0 = fmaf(es[(j + 0) * 64 + tid], dr[j + 0], v0);
            v1 = fmaf(es[(j + 1) * 64 + tid], dr[j + 1], v1);
            v2 = fmaf(es[(j + 2) * 64 + tid], dr[j + 2], v2);
            v3 = fmaf(es[(j + 3) * 64 + tid], dr[j + 3], v3);
        }
        for (; j < i; ++j) v0 = fmaf(es[j * 64 + tid], dr[j], v0);
        v += (v0 + v1) + (v2 + v3);
        es[i * 64 + tid] = tanhf(v * li[i]);
    }
    for (int i = 0; i < 128; ++i)
        split_store(g_AH, g_AL, b * 768 + 512 + i, es[i * 64 + tid]);
}

// ---------------- launch ----------------
extern "C" void kernel_launch(void* const* d_in, const int* in_sizes, int n_in,
                              void* d_out, int out_size) {
    (void)in_sizes; (void)n_in; (void)out_size;
    const float* w   = (const float*)d_in[1];
    const float* xi  = (const float*)d_in[2];
    const float* X   = (const float*)d_in[3];
    const float* Y   = (const float*)d_in[4];
    const float* B2  = (const float*)d_in[5];
    const float* C2  = (const float*)d_in[6];
    const float* D21 = (const float*)d_in[7];
    const float* D22 = (const float*)d_in[8];
    const float* D12 = (const float*)d_in[9];
    float* out   = (float*)d_out;
    float* out_u = out;
    float* out_x = out + (size_t)BATCHN * NIN;

    static cudaStream_t s2;
    static cudaEvent_t evFork, evJoin;
    static bool inited = false;
    if (!inited) {
        cudaStreamCreateWithFlags(&s2, cudaStreamNonBlocking);
        cudaEventCreateWithFlags(&evFork, cudaEventDisableTiming);
        cudaEventCreateWithFlags(&evJoin, cudaEventDisableTiming);
        inited = true;
    }

    float *pH, *pWout, *pPre, *pZf0, *pZf1;
    __nv_bfloat16 *pAH, *pAL, *pWpreH, *pWpreL, *pWoutH, *pWoutL;
    __nv_bfloat16 *pXtH, *pXtL, *pMH, *pML, *pTtH, *pTtL, *pRtH, *pRtL;
    __nv_bfloat16 *pZH[2], *pZL[2], *pZTH[2], *pZTL[2];
    cudaGetSymbolAddress((void**)&pH, g_H);
    cudaGetSymbolAddress((void**)&pWout, g_Wout);
    cudaGetSymbolAddress((void**)&pPre, g_pre);
    cudaGetSymbolAddress((void**)&pAH, g_AH);
    cudaGetSymbolAddress((void**)&pAL, g_AL);
    cudaGetSymbolAddress((void**)&pWpreH, g_WpreH);
    cudaGetSymbolAddress((void**)&pWpreL, g_WpreL);
    cudaGetSymbolAddress((void**)&pWoutH, g_WoutH);
    cudaGetSymbolAddress((void**)&pWoutL, g_WoutL);
    cudaGetSymbolAddress((void**)&pXtH, g_XtH);
    cudaGetSymbolAddress((void**)&pXtL, g_XtL);
    cudaGetSymbolAddress((void**)&pMH, g_MH);
    cudaGetSymbolAddress((void**)&pML, g_ML);
    cudaGetSymbolAddress((void**)&pTtH, g_TtH);
    cudaGetSymbolAddress((void**)&pTtL, g_TtL);
    cudaGetSymbolAddress((void**)&pRtH, g_RtH);
    cudaGetSymbolAddress((void**)&pRtL, g_RtL);
    {
        float* tmp;
        cudaGetSymbolAddress((void**)&tmp, g_Zf);
        pZf0 = tmp; pZf1 = tmp + NXI * NXI;
        __nv_bfloat16* t2;
        cudaGetSymbolAddress((void**)&t2, g_ZH);  pZH[0] = t2;  pZH[1] = t2 + NXI * NXI;
        cudaGetSymbolAddress((void**)&t2, g_ZL);  pZL[0] = t2;  pZL[1] = t2 + NXI * NXI;
        cudaGetSymbolAddress((void**)&t2, g_ZTH); pZTH[0] = t2; pZTH[1] = t2 + NXI * NXI;
        cudaGetSymbolAddress((void**)&t2, g_ZTL); pZTL[0] = t2; pZTL[1] = t2 + NXI * NXI;
    }

    // 0) A conversion (independent)
    conv_A<<<(BATCHN * 160 + 255) / 256, 256>>>(xi, w);
    // 1) split-transpose of X
    conv_Xt<<<dim3(HDIM / 32, HDIM / 32), dim3(32, 8)>>>(X);
    // 2) H = X^T X + eps*I   (tensor, split-bf16)
    tc2<<<dim3(HDIM / 64, HDIM / 64), 128>>>(
        pXtH, pXtL, pXtH, pXtL, HDIM, HDIM, HDIM,
        pH, HDIM, nullptr, nullptr, nullptr, nullptr, nullptr, 0);

    // ---- fork: branch B (Newton chain) on s2 ----
    cudaEventRecord(evFork, 0);
    cudaStreamWaitEvent(s2, evFork, 0);

    // ---- branch A (stream 0): Wpre -> pre-GEMM -> eps ----
    build_WpreSplit<<<(LDIM * 640 + 255) / 256, 256>>>(D12);
    build_D11<<<(LDIM * LDIM + 255) / 256, 256>>>();
    mma_gemm<<<dim3(1, BATCHN / 128), 256>>>(
        pAH, pAL, pWpreH, pWpreL, 20, 512, 128, 768, 768, pPre, nullptr, 0);
    eps_kernel<<<BATCHN / 64, 64>>>();

    // ---- branch B (s2): diag -> MZ -> Rt/WoutTop -> Newton -> Wout solve ----
    diag_kernel<<<2, 256, 0, s2>>>();
    build_MZ<<<(NXI * NXI + 255) / 256, 256, 0, s2>>>(Y);
    build_Rt<<<(NXI * 768 + 255) / 256, 256, 0, s2>>>(B2);
    build_WoutTop<<<(NIN * 768 + 255) / 256, 256, 0, s2>>>(C2, D21, D22);
    int cur = 0;
    for (int it = 0; it < NEWTON_ITERS; ++it) {
        // T = M * Z   (B operand = Z transposed splits) -> write Tt splits
        tc2<<<dim3(8, 8), 128, 0, s2>>>(
            pMH, pML, pZTH[cur], pZTL[cur], NXI, NXI, NXI,
            nullptr, 0, nullptr, nullptr, pTtH, pTtL, nullptr, 1);
        // Zn = 2Z - Z*T  (B operand = Tt splits)
        tc2<<<dim3(8, 8), 128, 0, s2>>>(
            pZH[cur], pZL[cur], pTtH, pTtL, NXI, NXI, NXI,
            (cur ? pZf0 : pZf1), NXI, pZH[1 - cur], pZL[1 - cur],
            pZTH[1 - cur], pZTL[1 - cur], (cur ? pZf1 : pZf0), 2);
        cur ^= 1;
    }
    // Wout rows 64..575 = Minv @ (D^-1 [Fm|B1|B2])
    tc2<<<dim3(768 / 64, NXI / 64), 128, 0, s2>>>(
        pZH[cur], pZL[cur], pRtH, pRtL, NXI, NXI, NXI,
        pWout + 64 * 768, 768, nullptr, nullptr, nullptr, nullptr, nullptr, 3);
    conv_Wout<<<(640 * 768 + 255) / 256, 256, 0, s2>>>();

    // ---- join ----
    cudaEventRecord(evJoin, s2);
    cudaStreamWaitEvent(0, evJoin, 0);

    // [u | xi_] = [xi|eps|w] @ Wout^T
    mma_gemm<<<dim3(5, BATCHN / 128), 256>>>(
        pAH, pAL, pWoutH, pWoutL, 24, 1 << 30, 0, 768, 768, out_u, out_x, 1);
}

// round 7
// speedup vs baseline: 2.9774x; 1.0163x over previous
#include <cuda_runtime.h>
#include <cuda_bf16.h>
#include <math.h>
#include <stdint.h>

#define NXI 512
#define LDIM 128
#define NSTATES 128
#define NIN 64
#define HDIM 1152           // 2*NXI + LDIM
#define BATCHN 32768
#define EPSV 0.001f
#define ALPHA 0.55f
#define NEWTON_ITERS 8      // + fused first step = 9 squarings

// ---------------- device scratch ----------------
__device__ float g_H[HDIM * HDIM];
__device__ float g_Zf[2][NXI * NXI];
__device__ float g_Wout[640 * 768];       // rows 576..639 stay zero (never written)
__device__ float g_D11[LDIM * LDIM];
__device__ float g_LamInv[LDIM];
__device__ float g_dinv[NXI];
__device__ float g_pre[(size_t)BATCHN * LDIM];

// split-bf16 operand arrays
__device__ __nv_bfloat16 g_AH[(size_t)BATCHN * 768];   // [xi | eps | w]
__device__ __nv_bfloat16 g_AL[(size_t)BATCHN * 768];
__device__ __nv_bfloat16 g_WpreH[LDIM * 768];
__device__ __nv_bfloat16 g_WpreL[LDIM * 768];
__device__ __nv_bfloat16 g_WoutH[640 * 768];
__device__ __nv_bfloat16 g_WoutL[640 * 768];
__device__ __nv_bfloat16 g_XtH[HDIM * HDIM];
__device__ __nv_bfloat16 g_XtL[HDIM * HDIM];
__device__ __nv_bfloat16 g_MH[NXI * NXI], g_ML[NXI * NXI];
__device__ __nv_bfloat16 g_ZH[2][NXI * NXI], g_ZL[2][NXI * NXI];
__device__ __nv_bfloat16 g_ZTH[2][NXI * NXI], g_ZTL[2][NXI * NXI];
__device__ __nv_bfloat16 g_TtH[NXI * NXI], g_TtL[NXI * NXI];
__device__ __nv_bfloat16 g_RtH[768 * NXI], g_RtL[768 * NXI];

// ---------------- PTX helpers ----------------
__device__ __forceinline__ uint32_t smem_u32(const void* p) {
    uint32_t a;
    asm("{ .reg .u64 t; cvta.to.shared.u64 t, %1; cvt.u32.u64 %0, t; }" : "=r"(a) : "l"(p));
    return a;
}
#define LDSM4(r0, r1, r2, r3, addr) \
    asm volatile("ldmatrix.sync.aligned.m8n8.x4.shared.b16 {%0,%1,%2,%3}, [%4];" \
                 : "=r"(r0), "=r"(r1), "=r"(r2), "=r"(r3) : "r"(addr))
#define MMA16816(d, a, b0, b1) \
    asm volatile("mma.sync.aligned.m16n8k16.row.col.f32.bf16.bf16.f32 " \
                 "{%0,%1,%2,%3},{%4,%5,%6,%7},{%8,%9},{%0,%1,%2,%3};" \
                 : "+f"(d[0]), "+f"(d[1]), "+f"(d[2]), "+f"(d[3]) \
                 : "r"(a[0]), "r"(a[1]), "r"(a[2]), "r"(a[3]), "r"(b0), "r"(b1))
#define CPA16(smaddr, gptr) \
    asm volatile("cp.async.cg.shared.global [%0], [%1], 16;" :: "r"(smaddr), "l"(gptr))
#define CPCOMMIT() asm volatile("cp.async.commit_group;" ::: "memory")
#define CPWAIT1()  asm volatile("cp.async.wait_group 1;" ::: "memory")
#define CPWAIT0()  asm volatile("cp.async.wait_group 0;" ::: "memory")

__device__ __forceinline__ void split_store(__nv_bfloat16* H, __nv_bfloat16* L, size_t idx, float v) {
    __nv_bfloat16 h = __float2bfloat16(v);
    H[idx] = h;
    L[idx] = __float2bfloat16(v - __bfloat162float(h));
}

// ============ big batch GEMM (128x128 tiles, cp.async 2-stage): out = A * W^T ============
#define BK 32
#define LDSW (BK + 8)
#define SA_AH 0
#define SA_AL 10240
#define SA_BH 20480
#define SA_BL 30720
#define SA_BUF 40960
__global__ __launch_bounds__(256) void mma_gemm(
    const __nv_bfloat16* __restrict__ Ah, const __nv_bfloat16* __restrict__ Al,
    const __nv_bfloat16* __restrict__ Bh, const __nv_bfloat16* __restrict__ Bl,
    int nchunks, int skip_at, int skip_amt, int lda, int ldb,
    float* __restrict__ out0, float* __restrict__ out1, int mode) {
    extern __shared__ char dsm[];
    const uint32_t smb = smem_u32(dsm);
    const int tid = threadIdx.x;
    const int wid = tid >> 5, lane = tid & 31;
    const size_t m0 = (size_t)blockIdx.y * 128;
    const int n0 = blockIdx.x * 128;
    const int wm = (wid & 3) * 32;
    const int wn = (wid >> 2) * 64;

    float acc[2][8][4] = {};
    const int lr = tid >> 1;
    const int lc = (tid & 1) * 16;
    const int am = wm + (lane & 15);
    const int ak = (lane >> 4) * 8;
    const int bn = wn + (lane & 7) + (lane >> 4) * 8;
    const int bk = ((lane >> 3) & 1) * 8;

    auto issue = [&](int c, int buf) {
        const int kc = c * BK;
        const int col = (kc >= skip_at) ? kc + skip_amt : kc;
        const size_t oa = (m0 + lr) * (size_t)lda + col + lc;
        const size_t ob = (size_t)(n0 + lr) * ldb + col + lc;
        const uint32_t so = smb + buf * SA_BUF + (uint32_t)(lr * LDSW + lc) * 2;
        CPA16(so + SA_AH, Ah + oa); CPA16(so + SA_AH + 16, Ah + oa + 8);
        CPA16(so + SA_AL, Al + oa); CPA16(so + SA_AL + 16, Al + oa + 8);
        CPA16(so + SA_BH, Bh + ob); CPA16(so + SA_BH + 16, Bh + ob + 8);
        CPA16(so + SA_BL, Bl + ob); CPA16(so + SA_BL + 16, Bl + ob + 8);
        CPCOMMIT();
    };

    issue(0, 0);
    for (int c = 0; c < nchunks; ++c) {
        if (c + 1 < nchunks) { issue(c + 1, (c + 1) & 1); CPWAIT1(); }
        else { CPWAIT0(); }
        __syncthreads();
        const uint32_t bb = smb + (c & 1) * SA_BUF;
#pragma unroll
        for (int k16 = 0; k16 < BK; k16 += 16) {
            uint32_t ahf[2][4], alf[2][4], bhf[4][4], blf[4][4];
#pragma unroll
            for (int mi = 0; mi < 2; ++mi) {
                const uint32_t off = bb + (uint32_t)(((am + mi * 16) * LDSW + ak + k16) * 2);
                LDSM4(ahf[mi][0], ahf[mi][1], ahf[mi][2], ahf[mi][3], off + SA_AH);
                LDSM4(alf[mi][0], alf[mi][1], alf[mi][2], alf[mi][3], off + SA_AL);
            }
#pragma unroll
            for (int j = 0; j < 4; ++j) {
                const uint32_t off = bb + (uint32_t)(((bn + j * 16) * LDSW + bk + k16) * 2);
                LDSM4(bhf[j][0], bhf[j][1], bhf[j][2], bhf[j][3], off + SA_BH);
                LDSM4(blf[j][0], blf[j][1], blf[j][2], blf[j][3], off + SA_BL);
            }
#pragma unroll
            for (int mi = 0; mi < 2; ++mi)
#pragma unroll
                for (int j = 0; j < 4; ++j)
#pragma unroll
                    for (int h = 0; h < 2; ++h) {
                        float* d = acc[mi][j * 2 + h];
                        MMA16816(d, ahf[mi], bhf[j][h * 2], bhf[j][h * 2 + 1]);
                        MMA16816(d, ahf[mi], blf[j][h * 2], blf[j][h * 2 + 1]);
                        MMA16816(d, alf[mi], bhf[j][h * 2], bhf[j][h * 2 + 1]);
                    }
        }
        __syncthreads();
    }
    const int rrow = lane >> 2;
    const int rcol = (lane & 3) * 2;
#pragma unroll
    for (int mi = 0; mi < 2; ++mi)
#pragma unroll
        for (int j = 0; j < 8; ++j) {
            const float* d = acc[mi][j];
            const int n = n0 + wn + j * 8 + rcol;
#pragma unroll
            for (int half = 0; half < 2; ++half) {
                const size_t m = m0 + wm + mi * 16 + rrow + half * 8;
                const float v0 = d[half * 2 + 0], v1 = d[half * 2 + 1];
                if (mode == 0) {
                    *(float2*)(out0 + m * 128 + n) = make_float2(v0, v1);
                } else {
                    if (n < NIN) *(float2*)(out0 + m * NIN + n) = make_float2(v0, v1);
                    else if (n < 576) *(float2*)(out1 + m * NXI + (n - NIN)) = make_float2(v0, v1);
                }
            }
        }
}

// ============ small tensor GEMM (64x64 tiles, 128 thr): C = A * B^T ============
// emode: 0 = H (+eps diag, fp32 out) ; 1 = T (transposed splits only)
//        2 = Newton Zn = 2*zin - C ; 3 = plain fp32 out
#define LDS2 (BK + 8)
__global__ __launch_bounds__(128) void tc2(
    const __nv_bfloat16* __restrict__ Ah, const __nv_bfloat16* __restrict__ Al,
    const __nv_bfloat16* __restrict__ Bh, const __nv_bfloat16* __restrict__ Bl,
    int K, int lda, int ldb,
    float* __restrict__ outf, int ldc,
    __nv_bfloat16* __restrict__ oH, __nv_bfloat16* __restrict__ oL,
    __nv_bfloat16* __restrict__ oTH, __nv_bfloat16* __restrict__ oTL,
    const float* __restrict__ zin, int emode) {
    __shared__ __nv_bfloat16 sAh[64 * LDS2], sAl[64 * LDS2];
    __shared__ __nv_bfloat16 sBh[64 * LDS2], sBl[64 * LDS2];
    const int tid = threadIdx.x;
    const int wid = tid >> 5, lane = tid & 31;
    const int m0 = blockIdx.y * 64;
    const int n0 = blockIdx.x * 64;
    const int wm = (wid & 1) * 32;
    const int wn = (wid >> 1) * 32;

    float acc[2][4][4] = {};
    const int lr = tid >> 1;
    const int lc = (tid & 1) * 16;
    const uint32_t uAh = smem_u32(sAh), uAl = smem_u32(sAl);
    const uint32_t uBh = smem_u32(sBh), uBl = smem_u32(sBl);
    const int am = wm + (lane & 15);
    const int ak = (lane >> 4) * 8;
    const int bn = wn + (lane & 7) + (lane >> 4) * 8;
    const int bk = ((lane >> 3) & 1) * 8;

    uint4 pa[2][2], pb[2][2];
    auto gload = [&](int c) {
        const int col = c * BK;
        const size_t oa = (size_t)(m0 + lr) * lda + col + lc;
        const size_t ob = (size_t)(n0 + lr) * ldb + col + lc;
        pa[0][0] = *(const uint4*)(Ah + oa); pa[0][1] = *(const uint4*)(Ah + oa + 8);
        pa[1][0] = *(const uint4*)(Al + oa); pa[1][1] = *(const uint4*)(Al + oa + 8);
        pb[0][0] = *(const uint4*)(Bh + ob); pb[0][1] = *(const uint4*)(Bh + ob + 8);
        pb[1][0] = *(const uint4*)(Bl + ob); pb[1][1] = *(const uint4*)(Bl + ob + 8);
    };

    const int nchunks = K / BK;
    gload(0);
    for (int c = 0; c < nchunks; ++c) {
        const int so = lr * LDS2 + lc;
        *(uint4*)(sAh + so) = pa[0][0]; *(uint4*)(sAh + so + 8) = pa[0][1];
        *(uint4*)(sAl + so) = pa[1][0]; *(uint4*)(sAl + so + 8) = pa[1][1];
        *(uint4*)(sBh + so) = pb[0][0]; *(uint4*)(sBh + so + 8) = pb[0][1];
        *(uint4*)(sBl + so) = pb[1][0]; *(uint4*)(sBl + so + 8) = pb[1][1];
        __syncthreads();
        if (c + 1 < nchunks) gload(c + 1);
#pragma unroll
        for (int k16 = 0; k16 < BK; k16 += 16) {
            uint32_t ahf[2][4], alf[2][4], bhf[2][4], blf[2][4];
#pragma unroll
            for (int mi = 0; mi < 2; ++mi) {
                const uint32_t off = (uint32_t)(((am + mi * 16) * LDS2 + ak + k16) * 2);
                LDSM4(ahf[mi][0], ahf[mi][1], ahf[mi][2], ahf[mi][3], uAh + off);
                LDSM4(alf[mi][0], alf[mi][1], alf[mi][2], alf[mi][3], uAl + off);
            }
#pragma unroll
            for (int j = 0; j < 2; ++j) {
                const uint32_t off = (uint32_t)(((bn + j * 16) * LDS2 + bk + k16) * 2);
                LDSM4(bhf[j][0], bhf[j][1], bhf[j][2], bhf[j][3], uBh + off);
                LDSM4(blf[j][0], blf[j][1], blf[j][2], blf[j][3], uBl + off);
            }
#pragma unroll
            for (int mi = 0; mi < 2; ++mi)
#pragma unroll
                for (int j = 0; j < 2; ++j)
#pragma unroll
                    for (int h = 0; h < 2; ++h) {
                        float* d = acc[mi][j * 2 + h];
                        MMA16816(d, ahf[mi], bhf[j][h * 2], bhf[j][h * 2 + 1]);
                        MMA16816(d, ahf[mi], blf[j][h * 2], blf[j][h * 2 + 1]);
                        MMA16816(d, alf[mi], bhf[j][h * 2], bhf[j][h * 2 + 1]);
                    }
        }
        __syncthreads();
    }
    const int rrow = lane >> 2;
    const int rcol = (lane & 3) * 2;
#pragma unroll
    for (int mi = 0; mi < 2; ++mi)
#pragma unroll
        for (int j = 0; j < 4; ++j) {
            const float* d = acc[mi][j];
            const int n = n0 + wn + j * 8 + rcol;
#pragma unroll
            for (int half = 0; half < 2; ++half) {
                const int m = m0 + wm + mi * 16 + rrow + half * 8;
                float v0 = d[half * 2 + 0], v1 = d[half * 2 + 1];
                if (emode == 0) {
                    if (m == n) v0 += EPSV;
                    if (m == n + 1) v1 += EPSV;
                    *(float2*)(outf + (size_t)m * ldc + n) = make_float2(v0, v1);
                } else if (emode == 1) {
                    split_store(oTH, oTL, (size_t)n * NXI + m, v0);
                    split_store(oTH, oTL, (size_t)(n + 1) * NXI + m, v1);
                } else if (emode == 2) {
                    const size_t o = (size_t)m * NXI + n;
                    v0 = 2.0f * zin[o] - v0;
                    v1 = 2.0f * zin[o + 1] - v1;
                    *(float2*)(outf + o) = make_float2(v0, v1);
                    split_store(oH, oL, o, v0);
                    split_store(oH, oL, o + 1, v1);
                    split_store(oTH, oTL, (size_t)n * NXI + m, v0);
                    split_store(oTH, oTL, (size_t)(n + 1) * NXI + m, v1);
                } else {
                    *(float2*)(outf + (size_t)m * ldc + n) = make_float2(v0, v1);
                }
            }
        }
}

// ---------------- builders ----------------
__global__ void conv_Xt(const float* __restrict__ X) {
    __shared__ float t[32][33];
    const int bx = blockIdx.x * 32, by = blockIdx.y * 32;
    const int tx = threadIdx.x, ty = threadIdx.y;
#pragma unroll
    for (int r = 0; r < 32; r += 8)
        t[ty + r][tx] = X[(size_t)(by + ty + r) * HDIM + bx + tx];
    __syncthreads();
#pragma unroll
    for (int r = 0; r < 32; r += 8) {
        const float v = t[tx][ty + r];
        split_store(g_XtH, g_XtL, (size_t)(bx + ty + r) * HDIM + by + tx, v);
    }
}
__global__ void diag_kernel() {
    int i = blockIdx.x * blockDim.x + threadIdx.x;
    if (i >= NXI) return;
    g_dinv[i] = 2.0f / (g_H[(size_t)i * HDIM + i] + g_H[(size_t)(640 + i) * HDIM + 640 + i]);
}
__global__ void build_MZ(const float* __restrict__ Y) {
    int idx = blockIdx.x * blockDim.x + threadIdx.x;
    if (idx >= NXI * NXI) return;
    int i = idx >> 9, j = idx & 511;
    float e = 0.5f * (g_H[(size_t)i * HDIM + j] + g_H[(size_t)(640 + i) * HDIM + 640 + j] +
                      Y[(size_t)i * NXI + j] - Y[(size_t)j * NXI + i]);
    float m = g_dinv[i] * e;
    split_store(g_MH, g_ML, idx, m);
    float z = ((i == j) ? 2.0f * ALPHA : 0.0f) - ALPHA * ALPHA * m;
    g_Zf[0][idx] = z;
    split_store(g_ZH[0], g_ZL[0], idx, z);
    split_store(g_ZTH[0], g_ZTL[0], (size_t)j * NXI + i, z);
}
__global__ void build_WpreSplit(const float* __restrict__ D12) {
    int idx = blockIdx.x * blockDim.x + threadIdx.x;
    if (idx >= LDIM * 640) return;
    int rr = idx / 640, c = idx - rr * 640;
    float v = (c < NXI) ? -g_H[(size_t)(NXI + rr) * HDIM + c] : D12[rr * NSTATES + (c - NXI)];
    int dc = (c < NXI) ? c : c + 128;
    split_store(g_WpreH, g_WpreL, (size_t)rr * 768 + dc, v);
}
__global__ void build_D11() {
    int idx = blockIdx.x * blockDim.x + threadIdx.x;
    if (idx >= LDIM * LDIM) return;
    int i = idx >> 7, j = idx & 127;
    g_D11[idx] = (j < i) ? -g_H[(size_t)(NXI + i) * HDIM + NXI + j] : 0.0f;
    if (j == i) g_LamInv[i] = 2.0f / g_H[(size_t)(NXI + i) * HDIM + NXI + i];
}
__global__ void build_Rt(const float* __restrict__ B2) {
    int idx = blockIdx.x * blockDim.x + threadIdx.x;
    if (idx >= NXI * 768) return;
    int i = idx / 768, c = idx - i * 768;
    float v = (c < 640) ? g_H[(size_t)(640 + i) * HDIM + c] : B2[i * NSTATES + (c - 640)];
    split_store(g_RtH, g_RtL, (size_t)c * NXI + i, g_dinv[i] * v);
}
__global__ void build_WoutTop(const float* __restrict__ C2, const float* __restrict__ D21,
                              const float* __restrict__ D22) {
    int idx = blockIdx.x * blockDim.x + threadIdx.x;
    if (idx >= NIN * 768) return;
    int rr = idx / 768, c = idx - rr * 768;
    g_Wout[idx] = (c < NXI) ? C2[rr * NXI + c]
                            : (c < 640 ? D21[rr * LDIM + (c - NXI)] : D22[rr * NSTATES + (c - 640)]);
}
__global__ void conv_Wout() {
    int idx = blockIdx.x * blockDim.x + threadIdx.x;
    if (idx >= 640 * 768) return;
    split_store(g_WoutH, g_WoutL, idx, g_Wout[idx]);
}
__global__ void conv_A(const float* __restrict__ xi, const float* __restrict__ w) {
    size_t idx = (size_t)blockIdx.x * blockDim.x + threadIdx.x;
    size_t b = idx / 160;
    int c0 = (int)(idx - b * 160) * 4;
    if (b >= BATCHN) return;
    float4 v;
    int dc;
    if (c0 < NXI) { v = *(const float4*)(xi + b * NXI + c0); dc = c0; }
    else          { v = *(const float4*)(w + b * NSTATES + (c0 - NXI)); dc = c0 + 128; }
    size_t o = b * 768 + dc;
    split_store(g_AH, g_AL, o + 0, v.x);
    split_store(g_AH, g_AL, o + 1, v.y);
    split_store(g_AH, g_AL, o + 2, v.z);
    split_store(g_AH, g_AL, o + 3, v.w);
}

// ---------------- tanh forward-substitution scan ----------------
__global__ __launch_bounds__(64) void eps_kernel() {
    __shared__ float es[128 * 64];
    __shared__ float li[128];
    int tid = threadIdx.x;
    size_t b = (size_t)blockIdx.x * 64 + tid;
    for (int i = tid; i < 128; i += 64) li[i] = g_LamInv[i];
    __syncthreads();
    for (int i = 0; i < 128; ++i) {
        float v = g_pre[b * 128 + i];
        const float* __restrict__ dr = &g_D11[i * 128];
        float v0 = 0.f, v1 = 0.f, v2 = 0.f, v3 = 0.f;
        int j = 0;
        for (; j + 3 < i; j += 4) {
            v0 = fmaf(es[(j + 0) * 64 + tid], dr[j + 0], v0);
            v1 = fmaf(es[(j + 1) * 64 + tid], dr[j + 1], v1);
            v2 = fmaf(es[(j + 2) * 64 + tid], dr[j + 2], v2);
            v3 = fmaf(es[(j + 3) * 64 + tid], dr[j + 3], v3);
        }
        for (; j < i; ++j) v0 = fmaf(es[j * 64 + tid], dr[j], v0);
        v += (v0 + v1) + (v2 + v3);
        es[i * 64 + tid] = tanhf(v * li[i]);
    }
    for (int i = 0; i < 128; ++i)
        split_store(g_AH, g_AL, b * 768 + 512 + i, es[i * 64 + tid]);
}

// ---------------- launch ----------------
extern "C" void kernel_launch(void* const* d_in, const int* in_sizes, int n_in,
                              void* d_out, int out_size) {
    (void)in_sizes; (void)n_in; (void)out_size;
    const float* w   = (const float*)d_in[1];
    const float* xi  = (const float*)d_in[2];
    const float* X   = (const float*)d_in[3];
    const float* Y   = (const float*)d_in[4];
    const float* B2  = (const float*)d_in[5];
    const float* C2  = (const float*)d_in[6];
    const float* D21 = (const float*)d_in[7];
    const float* D22 = (const float*)d_in[8];
    const float* D12 = (const float*)d_in[9];
    float* out   = (float*)d_out;
    float* out_u = out;
    float* out_x = out + (size_t)BATCHN * NIN;

    static cudaStream_t s2;
    static cudaEvent_t evStart, evH, evJoin;
    static bool inited = false;
    if (!inited) {
        cudaStreamCreateWithFlags(&s2, cudaStreamNonBlocking);
        cudaEventCreateWithFlags(&evStart, cudaEventDisableTiming);
        cudaEventCreateWithFlags(&evH, cudaEventDisableTiming);
        cudaEventCreateWithFlags(&evJoin, cudaEventDisableTiming);
        cudaFuncSetAttribute(mma_gemm, cudaFuncAttributeMaxDynamicSharedMemorySize, 2 * SA_BUF);
        inited = true;
    }

    float *pH, *pWout, *pPre, *pZf0, *pZf1;
    __nv_bfloat16 *pAH, *pAL, *pWpreH, *pWpreL, *pWoutH, *pWoutL;
    __nv_bfloat16 *pXtH, *pXtL, *pMH, *pML, *pTtH, *pTtL, *pRtH, *pRtL;
    __nv_bfloat16 *pZH[2], *pZL[2], *pZTH[2], *pZTL[2];
    cudaGetSymbolAddress((void**)&pH, g_H);
    cudaGetSymbolAddress((void**)&pWout, g_Wout);
    cudaGetSymbolAddress((void**)&pPre, g_pre);
    cudaGetSymbolAddress((void**)&pAH, g_AH);
    cudaGetSymbolAddress((void**)&pAL, g_AL);
    cudaGetSymbolAddress((void**)&pWpreH, g_WpreH);
    cudaGetSymbolAddress((void**)&pWpreL, g_WpreL);
    cudaGetSymbolAddress((void**)&pWoutH, g_WoutH);
    cudaGetSymbolAddress((void**)&pWoutL, g_WoutL);
    cudaGetSymbolAddress((void**)&pXtH, g_XtH);
    cudaGetSymbolAddress((void**)&pXtL, g_XtL);
    cudaGetSymbolAddress((void**)&pMH, g_MH);
    cudaGetSymbolAddress((void**)&pML, g_ML);
    cudaGetSymbolAddress((void**)&pTtH, g_TtH);
    cudaGetSymbolAddress((void**)&pTtL, g_TtL);
    cudaGetSymbolAddress((void**)&pRtH, g_RtH);
    cudaGetSymbolAddress((void**)&pRtL, g_RtL);
    {
        float* tmp;
        cudaGetSymbolAddress((void**)&tmp, g_Zf);
        pZf0 = tmp; pZf1 = tmp + NXI * NXI;
        __nv_bfloat16* t2;
        cudaGetSymbolAddress((void**)&t2, g_ZH);  pZH[0] = t2;  pZH[1] = t2 + NXI * NXI;
        cudaGetSymbolAddress((void**)&t2, g_ZL);  pZL[0] = t2;  pZL[1] = t2 + NXI * NXI;
        cudaGetSymbolAddress((void**)&t2, g_ZTH); pZTH[0] = t2; pZTH[1] = t2 + NXI * NXI;
        cudaGetSymbolAddress((void**)&t2, g_ZTL); pZTL[0] = t2; pZTL[1] = t2 + NXI * NXI;
    }

    // ---- top fork: conv_A on s2 in parallel with Xt/H on s0 ----
    cudaEventRecord(evStart, 0);
    cudaStreamWaitEvent(s2, evStart, 0);
    conv_A<<<(BATCHN * 160 + 255) / 256, 256, 0, s2>>>(xi, w);

    conv_Xt<<<dim3(HDIM / 32, HDIM / 32), dim3(32, 8)>>>(X);
    tc2<<<dim3(HDIM / 64, HDIM / 64), 128>>>(
        pXtH, pXtL, pXtH, pXtL, HDIM, HDIM, HDIM,
        pH, HDIM, nullptr, nullptr, nullptr, nullptr, nullptr, 0);
    cudaEventRecord(evH, 0);
    cudaStreamWaitEvent(s2, evH, 0);

    // ---- branch A (s2): Wpre/D11 -> pre-GEMM -> eps ----
    build_WpreSplit<<<(LDIM * 640 + 255) / 256, 256, 0, s2>>>(D12);
    build_D11<<<(LDIM * LDIM + 255) / 256, 256, 0, s2>>>();
    mma_gemm<<<dim3(1, BATCHN / 128), 256, 2 * SA_BUF, s2>>>(
        pAH, pAL, pWpreH, pWpreL, 20, 512, 128, 768, 768, pPre, nullptr, 0);
    eps_kernel<<<BATCHN / 64, 64, 0, s2>>>();
    cudaEventRecord(evJoin, s2);

    // ---- branch B (s0): diag -> MZ -> Rt/WoutTop -> Newton -> Wout solve ----
    diag_kernel<<<2, 256>>>();
    build_MZ<<<(NXI * NXI + 255) / 256, 256>>>(Y);
    build_Rt<<<(NXI * 768 + 255) / 256, 256>>>(B2);
    build_WoutTop<<<(NIN * 768 + 255) / 256, 256>>>(C2, D21, D22);
    int cur = 0;
    for (int it = 0; it < NEWTON_ITERS; ++it) {
        tc2<<<dim3(8, 8), 128>>>(
            pMH, pML, pZTH[cur], pZTL[cur], NXI, NXI, NXI,
            nullptr, 0, nullptr, nullptr, pTtH, pTtL, nullptr, 1);
        tc2<<<dim3(8, 8), 128>>>(
            pZH[cur], pZL[cur], pTtH, pTtL, NXI, NXI, NXI,
            (cur ? pZf0 : pZf1), NXI, pZH[1 - cur], pZL[1 - cur],
            pZTH[1 - cur], pZTL[1 - cur], (cur ? pZf1 : pZf0), 2);
        cur ^= 1;
    }
    tc2<<<dim3(768 / 64, NXI / 64), 128>>>(
        pZH[cur], pZL[cur], pRtH, pRtL, NXI, NXI, NXI,
        pWout + 64 * 768, 768, nullptr, nullptr, nullptr, nullptr, nullptr, 3);
    conv_Wout<<<(640 * 768 + 255) / 256, 256>>>();

    // ---- join ----
    cudaStreamWaitEvent(0, evJoin, 0);

    // [u | xi_] = [xi|eps|w] @ Wout^T
    mma_gemm<<<dim3(5, BATCHN / 128), 256, 2 * SA_BUF>>>(
        pAH, pAL, pWoutH, pWoutL, 24, 1 << 30, 0, 768, 768, out_u, out_x, 1);
}

// round 8
// speedup vs baseline: 3.5024x; 1.1763x over previous
#include <cuda_runtime.h>
#include <cuda_fp16.h>
#include <math.h>
#include <stdint.h>

#define NXI 512
#define LDIM 128
#define NSTATES 128
#define NIN 64
#define HDIM 1152           // 2*NXI + LDIM
#define BATCHN 32768
#define EPSV 0.001f
#define ALPHA 0.55f
#define NEWTON_ITERS 8      // + fused first step = 9 squarings

// ---------------- device scratch ----------------
__device__ float g_H[HDIM * HDIM];
__device__ float g_Zf[2][NXI * NXI];
__device__ float g_Wout[640 * 768];       // rows 576..639 stay zero (never written)
__device__ float g_D11[LDIM * LDIM];
__device__ float g_LamInv[LDIM];
__device__ float g_dinv[NXI];
__device__ float g_pre[(size_t)BATCHN * LDIM];

// split-fp16 operand arrays
__device__ __half g_AH[(size_t)BATCHN * 768];   // [xi | eps | w]
__device__ __half g_AL[(size_t)BATCHN * 768];
__device__ __half g_WpreH[LDIM * 768];
__device__ __half g_WpreL[LDIM * 768];
__device__ __half g_WoutH[640 * 768];
__device__ __half g_WoutL[640 * 768];
__device__ __half g_XtH[HDIM * HDIM];
__device__ __half g_XtL[HDIM * HDIM];
__device__ __half g_MH[NXI * NXI], g_ML[NXI * NXI];
__device__ __half g_ZH[2][NXI * NXI], g_ZL[2][NXI * NXI];
__device__ __half g_ZTH[2][NXI * NXI], g_ZTL[2][NXI * NXI];
__device__ __half g_TtH[NXI * NXI], g_TtL[NXI * NXI];
__device__ __half g_RtH[768 * NXI], g_RtL[768 * NXI];

// ---------------- PTX helpers ----------------
__device__ __forceinline__ uint32_t smem_u32(const void* p) {
    uint32_t a;
    asm("{ .reg .u64 t; cvta.to.shared.u64 t, %1; cvt.u32.u64 %0, t; }" : "=r"(a) : "l"(p));
    return a;
}
#define LDSM4(r0, r1, r2, r3, addr) \
    asm volatile("ldmatrix.sync.aligned.m8n8.x4.shared.b16 {%0,%1,%2,%3}, [%4];" \
                 : "=r"(r0), "=r"(r1), "=r"(r2), "=r"(r3) : "r"(addr))
#define MMA16816(d, a, b0, b1) \
    asm volatile("mma.sync.aligned.m16n8k16.row.col.f32.f16.f16.f32 " \
                 "{%0,%1,%2,%3},{%4,%5,%6,%7},{%8,%9},{%0,%1,%2,%3};" \
                 : "+f"(d[0]), "+f"(d[1]), "+f"(d[2]), "+f"(d[3]) \
                 : "r"(a[0]), "r"(a[1]), "r"(a[2]), "r"(a[3]), "r"(b0), "r"(b1))
#define CPA16(smaddr, gptr) \
    asm volatile("cp.async.cg.shared.global [%0], [%1], 16;" :: "r"(smaddr), "l"(gptr))
#define CPCOMMIT() asm volatile("cp.async.commit_group;" ::: "memory")
#define CPWAIT1()  asm volatile("cp.async.wait_group 1;" ::: "memory")
#define CPWAIT0()  asm volatile("cp.async.wait_group 0;" ::: "memory")

__device__ __forceinline__ void split_store(__half* H, __half* L, size_t idx, float v) {
    __half h = __float2half(v);
    H[idx] = h;
    L[idx] = __float2half(v - __half2float(h));
}

// ============ big batch GEMM (128x128 tiles, cp.async 2-stage): out = A * W^T ============
// NPROD==3: hh + h*l + l*h (full split). NPROD==2: hh + h_a*l_b (skip A-lo entirely).
#define BK 32
#define LDSW (BK + 8)
template <int NPROD>
__global__ __launch_bounds__(256) void mma_gemm(
    const __half* __restrict__ Ah, const __half* __restrict__ Al,
    const __half* __restrict__ Bh, const __half* __restrict__ Bl,
    int nchunks, int skip_at, int skip_amt, int lda, int ldb,
    float* __restrict__ out0, float* __restrict__ out1, int mode) {
    constexpr uint32_t SA_AH = 0;
    constexpr uint32_t SA_AL = (NPROD == 3) ? 10240 : 0;          // unused when 2
    constexpr uint32_t SA_BH = (NPROD == 3) ? 20480 : 10240;
    constexpr uint32_t SA_BL = (NPROD == 3) ? 30720 : 20480;
    constexpr uint32_t SBUF  = (NPROD == 3) ? 40960 : 30720;
    extern __shared__ char dsm[];
    const uint32_t smb = smem_u32(dsm);
    const int tid = threadIdx.x;
    const int wid = tid >> 5, lane = tid & 31;
    const size_t m0 = (size_t)blockIdx.y * 128;
    const int n0 = blockIdx.x * 128;
    const int wm = (wid & 3) * 32;
    const int wn = (wid >> 2) * 64;

    float acc[2][8][4] = {};
    const int lr = tid >> 1;
    const int lc = (tid & 1) * 16;
    const int am = wm + (lane & 15);
    const int ak = (lane >> 4) * 8;
    const int bn = wn + (lane & 7) + (lane >> 4) * 8;
    const int bk = ((lane >> 3) & 1) * 8;

    auto issue = [&](int c, int buf) {
        const int kc = c * BK;
        const int col = (kc >= skip_at) ? kc + skip_amt : kc;
        const size_t oa = (m0 + lr) * (size_t)lda + col + lc;
        const size_t ob = (size_t)(n0 + lr) * ldb + col + lc;
        const uint32_t so = smb + buf * SBUF + (uint32_t)(lr * LDSW + lc) * 2;
        CPA16(so + SA_AH, Ah + oa); CPA16(so + SA_AH + 16, Ah + oa + 8);
        if (NPROD == 3) { CPA16(so + SA_AL, Al + oa); CPA16(so + SA_AL + 16, Al + oa + 8); }
        CPA16(so + SA_BH, Bh + ob); CPA16(so + SA_BH + 16, Bh + ob + 8);
        CPA16(so + SA_BL, Bl + ob); CPA16(so + SA_BL + 16, Bl + ob + 8);
        CPCOMMIT();
    };

    issue(0, 0);
    for (int c = 0; c < nchunks; ++c) {
        if (c + 1 < nchunks) { issue(c + 1, (c + 1) & 1); CPWAIT1(); }
        else { CPWAIT0(); }
        __syncthreads();
        const uint32_t bb = smb + (c & 1) * SBUF;
#pragma unroll
        for (int k16 = 0; k16 < BK; k16 += 16) {
            uint32_t ahf[2][4], alf[2][4], bhf[4][4], blf[4][4];
#pragma unroll
            for (int mi = 0; mi < 2; ++mi) {
                const uint32_t off = bb + (uint32_t)(((am + mi * 16) * LDSW + ak + k16) * 2);
                LDSM4(ahf[mi][0], ahf[mi][1], ahf[mi][2], ahf[mi][3], off + SA_AH);
                if (NPROD == 3)
                    LDSM4(alf[mi][0], alf[mi][1], alf[mi][2], alf[mi][3], off + SA_AL);
            }
#pragma unroll
            for (int j = 0; j < 4; ++j) {
                const uint32_t off = bb + (uint32_t)(((bn + j * 16) * LDSW + bk + k16) * 2);
                LDSM4(bhf[j][0], bhf[j][1], bhf[j][2], bhf[j][3], off + SA_BH);
                LDSM4(blf[j][0], blf[j][1], blf[j][2], blf[j][3], off + SA_BL);
            }
#pragma unroll
            for (int mi = 0; mi < 2; ++mi)
#pragma unroll
                for (int j = 0; j < 4; ++j)
#pragma unroll
                    for (int h = 0; h < 2; ++h) {
                        float* d = acc[mi][j * 2 + h];
                        MMA16816(d, ahf[mi], bhf[j][h * 2], bhf[j][h * 2 + 1]);
                        MMA16816(d, ahf[mi], blf[j][h * 2], blf[j][h * 2 + 1]);
                        if (NPROD == 3)
                            MMA16816(d, alf[mi], bhf[j][h * 2], bhf[j][h * 2 + 1]);
                    }
        }
        __syncthreads();
    }
    const int rrow = lane >> 2;
    const int rcol = (lane & 3) * 2;
#pragma unroll
    for (int mi = 0; mi < 2; ++mi)
#pragma unroll
        for (int j = 0; j < 8; ++j) {
            const float* d = acc[mi][j];
            const int n = n0 + wn + j * 8 + rcol;
#pragma unroll
            for (int half = 0; half < 2; ++half) {
                const size_t m = m0 + wm + mi * 16 + rrow + half * 8;
                const float v0 = d[half * 2 + 0], v1 = d[half * 2 + 1];
                if (mode == 0) {
                    *(float2*)(out0 + m * 128 + n) = make_float2(v0, v1);
                } else {
                    if (n < NIN) *(float2*)(out0 + m * NIN + n) = make_float2(v0, v1);
                    else if (n < 576) *(float2*)(out1 + m * NXI + (n - NIN)) = make_float2(v0, v1);
                }
            }
        }
}

// ============ small tensor GEMM (64x64 tiles, 128 thr, fp16 3-product): C = A * B^T ============
// emode: 0 = H (+eps diag) ; 1 = transposed splits only ; 2 = Newton ; 3 = plain fp32
#define LDS2 (BK + 8)
__global__ __launch_bounds__(128) void tc2(
    const __half* __restrict__ Ah, const __half* __restrict__ Al,
    const __half* __restrict__ Bh, const __half* __restrict__ Bl,
    int K, int lda, int ldb,
    float* __restrict__ outf, int ldc,
    __half* __restrict__ oH, __half* __restrict__ oL,
    __half* __restrict__ oTH, __half* __restrict__ oTL,
    const float* __restrict__ zin, int emode) {
    __shared__ __half sAh[64 * LDS2], sAl[64 * LDS2];
    __shared__ __half sBh[64 * LDS2], sBl[64 * LDS2];
    const int tid = threadIdx.x;
    const int wid = tid >> 5, lane = tid & 31;
    const int m0 = blockIdx.y * 64;
    const int n0 = blockIdx.x * 64;
    const int wm = (wid & 1) * 32;
    const int wn = (wid >> 1) * 32;

    float acc[2][4][4] = {};
    const int lr = tid >> 1;
    const int lc = (tid & 1) * 16;
    const uint32_t uAh = smem_u32(sAh), uAl = smem_u32(sAl);
    const uint32_t uBh = smem_u32(sBh), uBl = smem_u32(sBl);
    const int am = wm + (lane & 15);
    const int ak = (lane >> 4) * 8;
    const int bn = wn + (lane & 7) + (lane >> 4) * 8;
    const int bk = ((lane >> 3) & 1) * 8;

    uint4 pa[2][2], pb[2][2];
    auto gload = [&](int c) {
        const int col = c * BK;
        const size_t oa = (size_t)(m0 + lr) * lda + col + lc;
        const size_t ob = (size_t)(n0 + lr) * ldb + col + lc;
        pa[0][0] = *(const uint4*)(Ah + oa); pa[0][1] = *(const uint4*)(Ah + oa + 8);
        pa[1][0] = *(const uint4*)(Al + oa); pa[1][1] = *(const uint4*)(Al + oa + 8);
        pb[0][0] = *(const uint4*)(Bh + ob); pb[0][1] = *(const uint4*)(Bh + ob + 8);
        pb[1][0] = *(const uint4*)(Bl + ob); pb[1][1] = *(const uint4*)(Bl + ob + 8);
    };

    const int nchunks = K / BK;
    gload(0);
    for (int c = 0; c < nchunks; ++c) {
        const int so = lr * LDS2 + lc;
        *(uint4*)(sAh + so) = pa[0][0]; *(uint4*)(sAh + so + 8) = pa[0][1];
        *(uint4*)(sAl + so) = pa[1][0]; *(uint4*)(sAl + so + 8) = pa[1][1];
        *(uint4*)(sBh + so) = pb[0][0]; *(uint4*)(sBh + so + 8) = pb[0][1];
        *(uint4*)(sBl + so) = pb[1][0]; *(uint4*)(sBl + so + 8) = pb[1][1];
        __syncthreads();
        if (c + 1 < nchunks) gload(c + 1);
#pragma unroll
        for (int k16 = 0; k16 < BK; k16 += 16) {
            uint32_t ahf[2][4], alf[2][4], bhf[2][4], blf[2][4];
#pragma unroll
            for (int mi = 0; mi < 2; ++mi) {
                const uint32_t off = (uint32_t)(((am + mi * 16) * LDS2 + ak + k16) * 2);
                LDSM4(ahf[mi][0], ahf[mi][1], ahf[mi][2], ahf[mi][3], uAh + off);
                LDSM4(alf[mi][0], alf[mi][1], alf[mi][2], alf[mi][3], uAl + off);
            }
#pragma unroll
            for (int j = 0; j < 2; ++j) {
                const uint32_t off = (uint32_t)(((bn + j * 16) * LDS2 + bk + k16) * 2);
                LDSM4(bhf[j][0], bhf[j][1], bhf[j][2], bhf[j][3], uBh + off);
                LDSM4(blf[j][0], blf[j][1], blf[j][2], blf[j][3], uBl + off);
            }
#pragma unroll
            for (int mi = 0; mi < 2; ++mi)
#pragma unroll
                for (int j = 0; j < 2; ++j)
#pragma unroll
                    for (int h = 0; h < 2; ++h) {
                        float* d = acc[mi][j * 2 + h];
                        MMA16816(d, ahf[mi], bhf[j][h * 2], bhf[j][h * 2 + 1]);
                        MMA16816(d, ahf[mi], blf[j][h * 2], blf[j][h * 2 + 1]);
                        MMA16816(d, alf[mi], bhf[j][h * 2], bhf[j][h * 2 + 1]);
                    }
        }
        __syncthreads();
    }
    const int rrow = lane >> 2;
    const int rcol = (lane & 3) * 2;
#pragma unroll
    for (int mi = 0; mi < 2; ++mi)
#pragma unroll
        for (int j = 0; j < 4; ++j) {
            const float* d = acc[mi][j];
            const int n = n0 + wn + j * 8 + rcol;
#pragma unroll
            for (int half = 0; half < 2; ++half) {
                const int m = m0 + wm + mi * 16 + rrow + half * 8;
                float v0 = d[half * 2 + 0], v1 = d[half * 2 + 1];
                if (emode == 0) {
                    if (m == n) v0 += EPSV;
                    if (m == n + 1) v1 += EPSV;
                    *(float2*)(outf + (size_t)m * ldc + n) = make_float2(v0, v1);
                } else if (emode == 1) {
                    split_store(oTH, oTL, (size_t)n * NXI + m, v0);
                    split_store(oTH, oTL, (size_t)(n + 1) * NXI + m, v1);
                } else if (emode == 2) {
                    const size_t o = (size_t)m * NXI + n;
                    v0 = 2.0f * zin[o] - v0;
                    v1 = 2.0f * zin[o + 1] - v1;
                    *(float2*)(outf + o) = make_float2(v0, v1);
                    split_store(oH, oL, o, v0);
                    split_store(oH, oL, o + 1, v1);
                    split_store(oTH, oTL, (size_t)n * NXI + m, v0);
                    split_store(oTH, oTL, (size_t)(n + 1) * NXI + m, v1);
                } else {
                    *(float2*)(outf + (size_t)m * ldc + n) = make_float2(v0, v1);
                }
            }
        }
}

// ---------------- builders ----------------
__global__ void conv_Xt(const float* __restrict__ X) {
    __shared__ float t[32][33];
    const int bx = blockIdx.x * 32, by = blockIdx.y * 32;
    const int tx = threadIdx.x, ty = threadIdx.y;
#pragma unroll
    for (int r = 0; r < 32; r += 8)
        t[ty + r][tx] = X[(size_t)(by + ty + r) * HDIM + bx + tx];
    __syncthreads();
#pragma unroll
    for (int r = 0; r < 32; r += 8) {
        const float v = t[tx][ty + r];
        split_store(g_XtH, g_XtL, (size_t)(bx + ty + r) * HDIM + by + tx, v);
    }
}
__global__ void diag_kernel() {
    int i = blockIdx.x * blockDim.x + threadIdx.x;
    if (i >= NXI) return;
    g_dinv[i] = 2.0f / (g_H[(size_t)i * HDIM + i] + g_H[(size_t)(640 + i) * HDIM + 640 + i]);
}
__global__ void build_MZ(const float* __restrict__ Y) {
    int idx = blockIdx.x * blockDim.x + threadIdx.x;
    if (idx >= NXI * NXI) return;
    int i = idx >> 9, j = idx & 511;
    float e = 0.5f * (g_H[(size_t)i * HDIM + j] + g_H[(size_t)(640 + i) * HDIM + 640 + j] +
                      Y[(size_t)i * NXI + j] - Y[(size_t)j * NXI + i]);
    float m = g_dinv[i] * e;
    split_store(g_MH, g_ML, idx, m);
    float z = ((i == j) ? 2.0f * ALPHA : 0.0f) - ALPHA * ALPHA * m;
    g_Zf[0][idx] = z;
    split_store(g_ZH[0], g_ZL[0], idx, z);
    split_store(g_ZTH[0], g_ZTL[0], (size_t)j * NXI + i, z);
}
__global__ void build_WpreSplit(const float* __restrict__ D12) {
    int idx = blockIdx.x * blockDim.x + threadIdx.x;
    if (idx >= LDIM * 640) return;
    int rr = idx / 640, c = idx - rr * 640;
    float v = (c < NXI) ? -g_H[(size_t)(NXI + rr) * HDIM + c] : D12[rr * NSTATES + (c - NXI)];
    int dc = (c < NXI) ? c : c + 128;
    split_store(g_WpreH, g_WpreL, (size_t)rr * 768 + dc, v);
}
__global__ void build_D11() {
    int idx = blockIdx.x * blockDim.x + threadIdx.x;
    if (idx >= LDIM * LDIM) return;
    int i = idx >> 7, j = idx & 127;
    g_D11[idx] = (j < i) ? -g_H[(size_t)(NXI + i) * HDIM + NXI + j] : 0.0f;
    if (j == i) g_LamInv[i] = 2.0f / g_H[(size_t)(NXI + i) * HDIM + NXI + i];
}
__global__ void build_Rt(const float* __restrict__ B2) {
    int idx = blockIdx.x * blockDim.x + threadIdx.x;
    if (idx >= NXI * 768) return;
    int i = idx / 768, c = idx - i * 768;
    float v = (c < 640) ? g_H[(size_t)(640 + i) * HDIM + c] : B2[i * NSTATES + (c - 640)];
    split_store(g_RtH, g_RtL, (size_t)c * NXI + i, g_dinv[i] * v);
}
__global__ void build_WoutTop(const float* __restrict__ C2, const float* __restrict__ D21,
                              const float* __restrict__ D22) {
    int idx = blockIdx.x * blockDim.x + threadIdx.x;
    if (idx >= NIN * 768) return;
    int rr = idx / 768, c = idx - rr * 768;
    g_Wout[idx] = (c < NXI) ? C2[rr * NXI + c]
                            : (c < 640 ? D21[rr * LDIM + (c - NXI)] : D22[rr * NSTATES + (c - 640)]);
}
__global__ void conv_Wout() {
    int idx = blockIdx.x * blockDim.x + threadIdx.x;
    if (idx >= 640 * 768) return;
    split_store(g_WoutH, g_WoutL, idx, g_Wout[idx]);
}
__global__ void conv_A(const float* __restrict__ xi, const float* __restrict__ w) {
    size_t idx = (size_t)blockIdx.x * blockDim.x + threadIdx.x;
    size_t b = idx / 160;
    int c0 = (int)(idx - b * 160) * 4;
    if (b >= BATCHN) return;
    float4 v;
    int dc;
    if (c0 < NXI) { v = *(const float4*)(xi + b * NXI + c0); dc = c0; }
    else          { v = *(const float4*)(w + b * NSTATES + (c0 - NXI)); dc = c0 + 128; }
    size_t o = b * 768 + dc;
    split_store(g_AH, g_AL, o + 0, v.x);
    split_store(g_AH, g_AL, o + 1, v.y);
    split_store(g_AH, g_AL, o + 2, v.z);
    split_store(g_AH, g_AL, o + 3, v.w);
}

// ---------------- tanh forward-substitution scan ----------------
__global__ __launch_bounds__(64) void eps_kernel() {
    __shared__ float es[128 * 64];
    __shared__ float li[128];
    int tid = threadIdx.x;
    size_t b = (size_t)blockIdx.x * 64 + tid;
    for (int i = tid; i < 128; i += 64) li[i] = g_LamInv[i];
    __syncthreads();
    for (int i = 0; i < 128; ++i) {
        float v = g_pre[b * 128 + i];
        const float* __restrict__ dr = &g_D11[i * 128];
        float v0 = 0.f, v1 = 0.f, v2 = 0.f, v3 = 0.f;
        int j = 0;
        for (; j + 3 < i; j += 4) {
            v0 = fmaf(es[(j + 0) * 64 + tid], dr[j + 0], v0);
            v1 = fmaf(es[(j + 1) * 64 + tid], dr[j + 1], v1);
            v2 = fmaf(es[(j + 2) * 64 + tid], dr[j + 2], v2);
            v3 = fmaf(es[(j + 3) * 64 + tid], dr[j + 3], v3);
        }
        for (; j < i; ++j) v0 = fmaf(es[j * 64 + tid], dr[j], v0);
        v += (v0 + v1) + (v2 + v3);
        es[i * 64 + tid] = tanhf(v * li[i]);
    }
    for (int i = 0; i < 128; ++i)
        split_store(g_AH, g_AL, b * 768 + 512 + i, es[i * 64 + tid]);
}

// ---------------- launch ----------------
extern "C" void kernel_launch(void* const* d_in, const int* in_sizes, int n_in,
                              void* d_out, int out_size) {
    (void)in_sizes; (void)n_in; (void)out_size;
    const float* w   = (const float*)d_in[1];
    const float* xi  = (const float*)d_in[2];
    const float* X   = (const float*)d_in[3];
    const float* Y   = (const float*)d_in[4];
    const float* B2  = (const float*)d_in[5];
    const float* C2  = (const float*)d_in[6];
    const float* D21 = (const float*)d_in[7];
    const float* D22 = (const float*)d_in[8];
    const float* D12 = (const float*)d_in[9];
    float* out   = (float*)d_out;
    float* out_u = out;
    float* out_x = out + (size_t)BATCHN * NIN;

    static cudaStream_t s2;
    static cudaEvent_t evStart, evH, evJoin;
    static bool inited = false;
    if (!inited) {
        cudaStreamCreateWithFlags(&s2, cudaStreamNonBlocking);
        cudaEventCreateWithFlags(&evStart, cudaEventDisableTiming);
        cudaEventCreateWithFlags(&evH, cudaEventDisableTiming);
        cudaEventCreateWithFlags(&evJoin, cudaEventDisableTiming);
        cudaFuncSetAttribute(mma_gemm<3>, cudaFuncAttributeMaxDynamicSharedMemorySize, 2 * 40960);
        cudaFuncSetAttribute(mma_gemm<2>, cudaFuncAttributeMaxDynamicSharedMemorySize, 2 * 30720);
        inited = true;
    }

    float *pH, *pWout, *pPre, *pZf0, *pZf1;
    __half *pAH, *pAL, *pWpreH, *pWpreL, *pWoutH, *pWoutL;
    __half *pXtH, *pXtL, *pMH, *pML, *pTtH, *pTtL, *pRtH, *pRtL;
    __half *pZH[2], *pZL[2], *pZTH[2], *pZTL[2];
    cudaGetSymbolAddress((void**)&pH, g_H);
    cudaGetSymbolAddress((void**)&pWout, g_Wout);
    cudaGetSymbolAddress((void**)&pPre, g_pre);
    cudaGetSymbolAddress((void**)&pAH, g_AH);
    cudaGetSymbolAddress((void**)&pAL, g_AL);
    cudaGetSymbolAddress((void**)&pWpreH, g_WpreH);
    cudaGetSymbolAddress((void**)&pWpreL, g_WpreL);
    cudaGetSymbolAddress((void**)&pWoutH, g_WoutH);
    cudaGetSymbolAddress((void**)&pWoutL, g_WoutL);
    cudaGetSymbolAddress((void**)&pXtH, g_XtH);
    cudaGetSymbolAddress((void**)&pXtL, g_XtL);
    cudaGetSymbolAddress((void**)&pMH, g_MH);
    cudaGetSymbolAddress((void**)&pML, g_ML);
    cudaGetSymbolAddress((void**)&pTtH, g_TtH);
    cudaGetSymbolAddress((void**)&pTtL, g_TtL);
    cudaGetSymbolAddress((void**)&pRtH, g_RtH);
    cudaGetSymbolAddress((void**)&pRtL, g_RtL);
    {
        float* tmp;
        cudaGetSymbolAddress((void**)&tmp, g_Zf);
        pZf0 = tmp; pZf1 = tmp + NXI * NXI;
        __half* t2;
        cudaGetSymbolAddress((void**)&t2, g_ZH);  pZH[0] = t2;  pZH[1] = t2 + NXI * NXI;
        cudaGetSymbolAddress((void**)&t2, g_ZL);  pZL[0] = t2;  pZL[1] = t2 + NXI * NXI;
        cudaGetSymbolAddress((void**)&t2, g_ZTH); pZTH[0] = t2; pZTH[1] = t2 + NXI * NXI;
        cudaGetSymbolAddress((void**)&t2, g_ZTL); pZTL[0] = t2; pZTL[1] = t2 + NXI * NXI;
    }

    // ---- top fork: conv_A on s2 in parallel with Xt/H on s0 ----
    cudaEventRecord(evStart, 0);
    cudaStreamWaitEvent(s2, evStart, 0);
    conv_A<<<(BATCHN * 160 + 255) / 256, 256, 0, s2>>>(xi, w);

    conv_Xt<<<dim3(HDIM / 32, HDIM / 32), dim3(32, 8)>>>(X);
    tc2<<<dim3(HDIM / 64, HDIM / 64), 128>>>(
        pXtH, pXtL, pXtH, pXtL, HDIM, HDIM, HDIM,
        pH, HDIM, nullptr, nullptr, nullptr, nullptr, nullptr, 0);
    cudaEventRecord(evH, 0);
    cudaStreamWaitEvent(s2, evH, 0);

    // ---- branch A (s2): Wpre/D11 -> pre-GEMM (3-product) -> eps ----
    build_WpreSplit<<<(LDIM * 640 + 255) / 256, 256, 0, s2>>>(D12);
    build_D11<<<(LDIM * LDIM + 255) / 256, 256, 0, s2>>>();
    mma_gemm<3><<<dim3(1, BATCHN / 128), 256, 2 * 40960, s2>>>(
        pAH, pAL, pWpreH, pWpreL, 20, 512, 128, 768, 768, pPre, nullptr, 0);
    eps_kernel<<<BATCHN / 64, 64, 0, s2>>>();
    cudaEventRecord(evJoin, s2);

    // ---- branch B (s0): diag -> MZ -> Rt/WoutTop -> Newton -> Wout solve ----
    diag_kernel<<<2, 256>>>();
    build_MZ<<<(NXI * NXI + 255) / 256, 256>>>(Y);
    build_Rt<<<(NXI * 768 + 255) / 256, 256>>>(B2);
    build_WoutTop<<<(NIN * 768 + 255) / 256, 256>>>(C2, D21, D22);
    int cur = 0;
    for (int it = 0; it < NEWTON_ITERS; ++it) {
        tc2<<<dim3(8, 8), 128>>>(
            pMH, pML, pZTH[cur], pZTL[cur], NXI, NXI, NXI,
            nullptr, 0, nullptr, nullptr, pTtH, pTtL, nullptr, 1);
        tc2<<<dim3(8, 8), 128>>>(
            pZH[cur], pZL[cur], pTtH, pTtL, NXI, NXI, NXI,
            (cur ? pZf0 : pZf1), NXI, pZH[1 - cur], pZL[1 - cur],
            pZTH[1 - cur], pZTL[1 - cur], (cur ? pZf1 : pZf0), 2);
        cur ^= 1;
    }
    tc2<<<dim3(768 / 64, NXI / 64), 128>>>(
        pZH[cur], pZL[cur], pRtH, pRtL, NXI, NXI, NXI,
        pWout + 64 * 768, 768, nullptr, nullptr, nullptr, nullptr, nullptr, 3);
    conv_Wout<<<(640 * 768 + 255) / 256, 256>>>();

    // ---- join ----
    cudaStreamWaitEvent(0, evJoin, 0);

    // [u | xi_] = [xi|eps|w] @ Wout^T  (2-product fp16 split)
    mma_gemm<2><<<dim3(5, BATCHN / 128), 256, 2 * 30720>>>(
        pAH, pAL, pWoutH, pWoutL, 24, 1 << 30, 0, 768, 768, out_u, out_x, 1);
}

// round 9
// speedup vs baseline: 3.5845x; 1.0234x over previous
#include <cuda_runtime.h>
#include <cuda_fp16.h>
#include <math.h>
#include <stdint.h>

#define NXI 512
#define LDIM 128
#define NSTATES 128
#define NIN 64
#define HDIM 1152           // 2*NXI + LDIM
#define BATCHN 32768
#define EPSV 0.001f
#define ALPHA 0.55f
#define NEWTON_ITERS 7      // + fused first step = 8 squarings

// ---------------- device scratch ----------------
__device__ float g_H[HDIM * HDIM];
__device__ float g_Zf[2][NXI * NXI];
__device__ float g_D11[LDIM * LDIM];
__device__ float g_LamInv[LDIM];
__device__ float g_dinv[NXI];
__device__ float g_pre[(size_t)BATCHN * LDIM];
__device__ unsigned g_barcnt, g_barep;     // software grid barrier state (zero-init)

// split-fp16 operand arrays
__device__ __half g_AH[(size_t)BATCHN * 768];   // [xi | eps | w]
__device__ __half g_AL[(size_t)BATCHN * 768];
__device__ __half g_WpreH[LDIM * 768];
__device__ __half g_WpreL[LDIM * 768];
__device__ __half g_WoutH[640 * 768];           // rows 576..639 stay zero
__device__ __half g_WoutL[640 * 768];
__device__ __half g_XtH[HDIM * HDIM];
__device__ __half g_XtL[HDIM * HDIM];
__device__ __half g_MH[NXI * NXI], g_ML[NXI * NXI];
__device__ __half g_ZH[2][NXI * NXI], g_ZL[2][NXI * NXI];
__device__ __half g_ZTH[2][NXI * NXI], g_ZTL[2][NXI * NXI];
__device__ __half g_TtH[NXI * NXI], g_TtL[NXI * NXI];
__device__ __half g_RtH[768 * NXI], g_RtL[768 * NXI];

// ---------------- PTX helpers ----------------
__device__ __forceinline__ uint32_t smem_u32(const void* p) {
    uint32_t a;
    asm("{ .reg .u64 t; cvta.to.shared.u64 t, %1; cvt.u32.u64 %0, t; }" : "=r"(a) : "l"(p));
    return a;
}
#define LDSM4(r0, r1, r2, r3, addr) \
    asm volatile("ldmatrix.sync.aligned.m8n8.x4.shared.b16 {%0,%1,%2,%3}, [%4];" \
                 : "=r"(r0), "=r"(r1), "=r"(r2), "=r"(r3) : "r"(addr))
#define MMA16816(d, a, b0, b1) \
    asm volatile("mma.sync.aligned.m16n8k16.row.col.f32.f16.f16.f32 " \
                 "{%0,%1,%2,%3},{%4,%5,%6,%7},{%8,%9},{%0,%1,%2,%3};" \
                 : "+f"(d[0]), "+f"(d[1]), "+f"(d[2]), "+f"(d[3]) \
                 : "r"(a[0]), "r"(a[1]), "r"(a[2]), "r"(a[3]), "r"(b0), "r"(b1))
#define CPA16(smaddr, gptr) \
    asm volatile("cp.async.cg.shared.global [%0], [%1], 16;" :: "r"(smaddr), "l"(gptr))
#define CPCOMMIT() asm volatile("cp.async.commit_group;" ::: "memory")
#define CPWAIT1()  asm volatile("cp.async.wait_group 1;" ::: "memory")
#define CPWAIT0()  asm volatile("cp.async.wait_group 0;" ::: "memory")

__device__ __forceinline__ void split_store(__half* H, __half* L, size_t idx, float v) {
    __half h = __float2half(v);
    H[idx] = h;
    L[idx] = __float2half(v - __half2float(h));
}

// software grid barrier (all NBLK CTAs co-resident). Replay-safe: count returns
// to 0 each barrier; epoch compared by equality (wrap-safe).
__device__ __forceinline__ void gridbar(int nblk) {
    __threadfence();
    __syncthreads();
    if (threadIdx.x == 0) {
        unsigned e = ((volatile unsigned*)&g_barep)[0];
        unsigned t = atomicAdd(&g_barcnt, 1);
        if (t == (unsigned)nblk - 1) {
            g_barcnt = 0;
            __threadfence();
            atomicAdd(&g_barep, 1);
        } else {
            while (((volatile unsigned*)&g_barep)[0] == e) {}
        }
    }
    __syncthreads();
    __threadfence();
}

// ============ big batch GEMM (128x128 tiles, cp.async 2-stage): out = A * W^T ============
// NPROD==3: hh + h*l + l*h. NPROD==2: hh + h_a*l_b (skip A-lo).
#define BK 32
#define LDSW (BK + 8)
template <int NPROD>
__global__ __launch_bounds__(256) void mma_gemm(
    const __half* __restrict__ Ah, const __half* __restrict__ Al,
    const __half* __restrict__ Bh, const __half* __restrict__ Bl,
    int nchunks, int skip_at, int skip_amt, int lda, int ldb,
    float* __restrict__ out0, float* __restrict__ out1, int mode) {
    constexpr uint32_t SA_AH = 0;
    constexpr uint32_t SA_AL = (NPROD == 3) ? 10240 : 0;
    constexpr uint32_t SA_BH = (NPROD == 3) ? 20480 : 10240;
    constexpr uint32_t SA_BL = (NPROD == 3) ? 30720 : 20480;
    constexpr uint32_t SBUF  = (NPROD == 3) ? 40960 : 30720;
    extern __shared__ char dsm[];
    const uint32_t smb = smem_u32(dsm);
    const int tid = threadIdx.x;
    const int wid = tid >> 5, lane = tid & 31;
    const size_t m0 = (size_t)blockIdx.y * 128;
    const int n0 = blockIdx.x * 128;
    const int wm = (wid & 3) * 32;
    const int wn = (wid >> 2) * 64;

    float acc[2][8][4] = {};
    const int lr = tid >> 1;
    const int lc = (tid & 1) * 16;
    const int am = wm + (lane & 15);
    const int ak = (lane >> 4) * 8;
    const int bn = wn + (lane & 7) + (lane >> 4) * 8;
    const int bk = ((lane >> 3) & 1) * 8;

    auto issue = [&](int c, int buf) {
        const int kc = c * BK;
        const int col = (kc >= skip_at) ? kc + skip_amt : kc;
        const size_t oa = (m0 + lr) * (size_t)lda + col + lc;
        const size_t ob = (size_t)(n0 + lr) * ldb + col + lc;
        const uint32_t so = smb + buf * SBUF + (uint32_t)(lr * LDSW + lc) * 2;
        CPA16(so + SA_AH, Ah + oa); CPA16(so + SA_AH + 16, Ah + oa + 8);
        if (NPROD == 3) { CPA16(so + SA_AL, Al + oa); CPA16(so + SA_AL + 16, Al + oa + 8); }
        CPA16(so + SA_BH, Bh + ob); CPA16(so + SA_BH + 16, Bh + ob + 8);
        CPA16(so + SA_BL, Bl + ob); CPA16(so + SA_BL + 16, Bl + ob + 8);
        CPCOMMIT();
    };

    issue(0, 0);
    for (int c = 0; c < nchunks; ++c) {
        if (c + 1 < nchunks) { issue(c + 1, (c + 1) & 1); CPWAIT1(); }
        else { CPWAIT0(); }
        __syncthreads();
        const uint32_t bb = smb + (c & 1) * SBUF;
#pragma unroll
        for (int k16 = 0; k16 < BK; k16 += 16) {
            uint32_t ahf[2][4], alf[2][4], bhf[4][4], blf[4][4];
#pragma unroll
            for (int mi = 0; mi < 2; ++mi) {
                const uint32_t off = bb + (uint32_t)(((am + mi * 16) * LDSW + ak + k16) * 2);
                LDSM4(ahf[mi][0], ahf[mi][1], ahf[mi][2], ahf[mi][3], off + SA_AH);
                if (NPROD == 3)
                    LDSM4(alf[mi][0], alf[mi][1], alf[mi][2], alf[mi][3], off + SA_AL);
            }
#pragma unroll
            for (int j = 0; j < 4; ++j) {
                const uint32_t off = bb + (uint32_t)(((bn + j * 16) * LDSW + bk + k16) * 2);
                LDSM4(bhf[j][0], bhf[j][1], bhf[j][2], bhf[j][3], off + SA_BH);
                LDSM4(blf[j][0], blf[j][1], blf[j][2], blf[j][3], off + SA_BL);
            }
#pragma unroll
            for (int mi = 0; mi < 2; ++mi)
#pragma unroll
                for (int j = 0; j < 4; ++j)
#pragma unroll
                    for (int h = 0; h < 2; ++h) {
                        float* d = acc[mi][j * 2 + h];
                        MMA16816(d, ahf[mi], bhf[j][h * 2], bhf[j][h * 2 + 1]);
                        MMA16816(d, ahf[mi], blf[j][h * 2], blf[j][h * 2 + 1]);
                        if (NPROD == 3)
                            MMA16816(d, alf[mi], bhf[j][h * 2], bhf[j][h * 2 + 1]);
                    }
        }
        __syncthreads();
    }
    const int rrow = lane >> 2;
    const int rcol = (lane & 3) * 2;
#pragma unroll
    for (int mi = 0; mi < 2; ++mi)
#pragma unroll
        for (int j = 0; j < 8; ++j) {
            const float* d = acc[mi][j];
            const int n = n0 + wn + j * 8 + rcol;
#pragma unroll
            for (int half = 0; half < 2; ++half) {
                const size_t m = m0 + wm + mi * 16 + rrow + half * 8;
                const float v0 = d[half * 2 + 0], v1 = d[half * 2 + 1];
                if (mode == 0) {
                    *(float2*)(out0 + m * 128 + n) = make_float2(v0, v1);
                } else {
                    if (n < NIN) *(float2*)(out0 + m * NIN + n) = make_float2(v0, v1);
                    else if (n < 576) *(float2*)(out1 + m * NXI + (n - NIN)) = make_float2(v0, v1);
                }
            }
        }
}

// ============ 64x64 GEMM core (fp16 3-product), shared by tc2 and newton_fused ============
#define LDS2 (BK + 8)
__device__ __forceinline__ void gemm64_core(
    const __half* __restrict__ Ah, const __half* __restrict__ Al,
    const __half* __restrict__ Bh, const __half* __restrict__ Bl,
    int K, int lda, int ldb, int m0, int n0,
    __half* sAh, __half* sAl, __half* sBh, __half* sBl,
    float acc[2][4][4]) {
    const int tid = threadIdx.x;
    const int wid = tid >> 5, lane = tid & 31;
    const int wm = (wid & 1) * 32;
    const int wn = (wid >> 1) * 32;
    const int lr = tid >> 1;
    const int lc = (tid & 1) * 16;
    const uint32_t uAh = smem_u32(sAh), uAl = smem_u32(sAl);
    const uint32_t uBh = smem_u32(sBh), uBl = smem_u32(sBl);
    const int am = wm + (lane & 15);
    const int ak = (lane >> 4) * 8;
    const int bn = wn + (lane & 7) + (lane >> 4) * 8;
    const int bk = ((lane >> 3) & 1) * 8;

#pragma unroll
    for (int mi = 0; mi < 2; ++mi)
#pragma unroll
        for (int j = 0; j < 4; ++j)
#pragma unroll
            for (int q = 0; q < 4; ++q) acc[mi][j][q] = 0.0f;

    uint4 pa[2][2], pb[2][2];
    auto gload = [&](int c) {
        const int col = c * BK;
        const size_t oa = (size_t)(m0 + lr) * lda + col + lc;
        const size_t ob = (size_t)(n0 + lr) * ldb + col + lc;
        pa[0][0] = *(const uint4*)(Ah + oa); pa[0][1] = *(const uint4*)(Ah + oa + 8);
        pa[1][0] = *(const uint4*)(Al + oa); pa[1][1] = *(const uint4*)(Al + oa + 8);
        pb[0][0] = *(const uint4*)(Bh + ob); pb[0][1] = *(const uint4*)(Bh + ob + 8);
        pb[1][0] = *(const uint4*)(Bl + ob); pb[1][1] = *(const uint4*)(Bl + ob + 8);
    };

    const int nchunks = K / BK;
    gload(0);
    for (int c = 0; c < nchunks; ++c) {
        const int so = lr * LDS2 + lc;
        *(uint4*)(sAh + so) = pa[0][0]; *(uint4*)(sAh + so + 8) = pa[0][1];
        *(uint4*)(sAl + so) = pa[1][0]; *(uint4*)(sAl + so + 8) = pa[1][1];
        *(uint4*)(sBh + so) = pb[0][0]; *(uint4*)(sBh + so + 8) = pb[0][1];
        *(uint4*)(sBl + so) = pb[1][0]; *(uint4*)(sBl + so + 8) = pb[1][1];
        __syncthreads();
        if (c + 1 < nchunks) gload(c + 1);
#pragma unroll
        for (int k16 = 0; k16 < BK; k16 += 16) {
            uint32_t ahf[2][4], alf[2][4], bhf[2][4], blf[2][4];
#pragma unroll
            for (int mi = 0; mi < 2; ++mi) {
                const uint32_t off = (uint32_t)(((am + mi * 16) * LDS2 + ak + k16) * 2);
                LDSM4(ahf[mi][0], ahf[mi][1], ahf[mi][2], ahf[mi][3], uAh + off);
                LDSM4(alf[mi][0], alf[mi][1], alf[mi][2], alf[mi][3], uAl + off);
            }
#pragma unroll
            for (int j = 0; j < 2; ++j) {
                const uint32_t off = (uint32_t)(((bn + j * 16) * LDS2 + bk + k16) * 2);
                LDSM4(bhf[j][0], bhf[j][1], bhf[j][2], bhf[j][3], uBh + off);
                LDSM4(blf[j][0], blf[j][1], blf[j][2], blf[j][3], uBl + off);
            }
#pragma unroll
            for (int mi = 0; mi < 2; ++mi)
#pragma unroll
                for (int j = 0; j < 2; ++j)
#pragma unroll
                    for (int h = 0; h < 2; ++h) {
                        float* d = acc[mi][j * 2 + h];
                        MMA16816(d, ahf[mi], bhf[j][h * 2], bhf[j][h * 2 + 1]);
                        MMA16816(d, ahf[mi], blf[j][h * 2], blf[j][h * 2 + 1]);
                        MMA16816(d, alf[mi], bhf[j][h * 2], bhf[j][h * 2 + 1]);
                    }
        }
        __syncthreads();
    }
}

// standalone small GEMM. emode 0 = H (+eps diag) ; 3 = fp32 out (if outf) + splits (if oH)
__global__ __launch_bounds__(128) void tc2(
    const __half* __restrict__ Ah, const __half* __restrict__ Al,
    const __half* __restrict__ Bh, const __half* __restrict__ Bl,
    int K, int lda, int ldb,
    float* __restrict__ outf, int ldc,
    __half* __restrict__ oH, __half* __restrict__ oL, int emode) {
    __shared__ __half sAh[64 * LDS2], sAl[64 * LDS2];
    __shared__ __half sBh[64 * LDS2], sBl[64 * LDS2];
    const int tid = threadIdx.x;
    const int wid = tid >> 5, lane = tid & 31;
    const int m0 = blockIdx.y * 64;
    const int n0 = blockIdx.x * 64;
    const int wm = (wid & 1) * 32;
    const int wn = (wid >> 1) * 32;
    float acc[2][4][4];
    gemm64_core(Ah, Al, Bh, Bl, K, lda, ldb, m0, n0, sAh, sAl, sBh, sBl, acc);

    const int rrow = lane >> 2;
    const int rcol = (lane & 3) * 2;
#pragma unroll
    for (int mi = 0; mi < 2; ++mi)
#pragma unroll
        for (int j = 0; j < 4; ++j) {
            const float* d = acc[mi][j];
            const int n = n0 + wn + j * 8 + rcol;
#pragma unroll
            for (int half = 0; half < 2; ++half) {
                const int m = m0 + wm + mi * 16 + rrow + half * 8;
                float v0 = d[half * 2 + 0], v1 = d[half * 2 + 1];
                if (emode == 0) {
                    if (m == n) v0 += EPSV;
                    if (m == n + 1) v1 += EPSV;
                    *(float2*)(outf + (size_t)m * ldc + n) = make_float2(v0, v1);
                } else {
                    const size_t o = (size_t)m * ldc + n;
                    if (outf) *(float2*)(outf + o) = make_float2(v0, v1);
                    if (oH) { split_store(oH, oL, o, v0); split_store(oH, oL, o + 1, v1); }
                }
            }
        }
}

// ============ fused persistent Newton chain: one launch, software grid barrier ============
#define NWT_BLOCKS 64
__global__ __launch_bounds__(128) void newton_fused() {
    __shared__ __half sAh[64 * LDS2], sAl[64 * LDS2];
    __shared__ __half sBh[64 * LDS2], sBl[64 * LDS2];
    const int tid = threadIdx.x;
    const int wid = tid >> 5, lane = tid & 31;
    const int m0 = (blockIdx.x >> 3) * 64;
    const int n0 = (blockIdx.x & 7) * 64;
    const int wm = (wid & 1) * 32;
    const int wn = (wid >> 1) * 32;
    const int rrow = lane >> 2;
    const int rcol = (lane & 3) * 2;
    float acc[2][4][4];

    int cur = 0;
    for (int it = 0; it < NEWTON_ITERS; ++it) {
        // phase 1: T = M * Z^T(desc)  -> write transposed splits Tt
        gemm64_core(g_MH, g_ML, g_ZTH[cur], g_ZTL[cur], NXI, NXI, NXI, m0, n0,
                    sAh, sAl, sBh, sBl, acc);
#pragma unroll
        for (int mi = 0; mi < 2; ++mi)
#pragma unroll
            for (int j = 0; j < 4; ++j) {
                const float* d = acc[mi][j];
                const int n = n0 + wn + j * 8 + rcol;
#pragma unroll
                for (int half = 0; half < 2; ++half) {
                    const int m = m0 + wm + mi * 16 + rrow + half * 8;
                    split_store(g_TtH, g_TtL, (size_t)n * NXI + m, d[half * 2 + 0]);
                    split_store(g_TtH, g_TtL, (size_t)(n + 1) * NXI + m, d[half * 2 + 1]);
                }
            }
        gridbar(NWT_BLOCKS);

        // phase 2: Zn = 2*Z - Z*T  -> fp32 + row splits + transposed splits
        gemm64_core(g_ZH[cur], g_ZL[cur], g_TtH, g_TtL, NXI, NXI, NXI, m0, n0,
                    sAh, sAl, sBh, sBl, acc);
        const float* zin = g_Zf[cur];
        float* zout = g_Zf[cur ^ 1];
        const int nx = cur ^ 1;
#pragma unroll
        for (int mi = 0; mi < 2; ++mi)
#pragma unroll
            for (int j = 0; j < 4; ++j) {
                const float* d = acc[mi][j];
                const int n = n0 + wn + j * 8 + rcol;
#pragma unroll
                for (int half = 0; half < 2; ++half) {
                    const int m = m0 + wm + mi * 16 + rrow + half * 8;
                    const size_t o = (size_t)m * NXI + n;
                    float v0 = 2.0f * zin[o] - d[half * 2 + 0];
                    float v1 = 2.0f * zin[o + 1] - d[half * 2 + 1];
                    *(float2*)(zout + o) = make_float2(v0, v1);
                    split_store(g_ZH[nx], g_ZL[nx], o, v0);
                    split_store(g_ZH[nx], g_ZL[nx], o + 1, v1);
                    split_store(g_ZTH[nx], g_ZTL[nx], (size_t)n * NXI + m, v0);
                    split_store(g_ZTH[nx], g_ZTL[nx], (size_t)(n + 1) * NXI + m, v1);
                }
            }
        gridbar(NWT_BLOCKS);
        cur ^= 1;
    }
}

// ---------------- builders ----------------
__global__ void conv_Xt(const float* __restrict__ X) {
    __shared__ float t[32][33];
    const int bx = blockIdx.x * 32, by = blockIdx.y * 32;
    const int tx = threadIdx.x, ty = threadIdx.y;
#pragma unroll
    for (int r = 0; r < 32; r += 8)
        t[ty + r][tx] = X[(size_t)(by + ty + r) * HDIM + bx + tx];
    __syncthreads();
#pragma unroll
    for (int r = 0; r < 32; r += 8) {
        const float v = t[tx][ty + r];
        split_store(g_XtH, g_XtL, (size_t)(bx + ty + r) * HDIM + by + tx, v);
    }
}
__global__ void diag_kernel() {
    int i = blockIdx.x * blockDim.x + threadIdx.x;
    if (i >= NXI) return;
    g_dinv[i] = 2.0f / (g_H[(size_t)i * HDIM + i] + g_H[(size_t)(640 + i) * HDIM + 640 + i]);
}
__global__ void build_MZ(const float* __restrict__ Y) {
    int idx = blockIdx.x * blockDim.x + threadIdx.x;
    if (idx >= NXI * NXI) return;
    int i = idx >> 9, j = idx & 511;
    float e = 0.5f * (g_H[(size_t)i * HDIM + j] + g_H[(size_t)(640 + i) * HDIM + 640 + j] +
                      Y[(size_t)i * NXI + j] - Y[(size_t)j * NXI + i]);
    float m = g_dinv[i] * e;
    split_store(g_MH, g_ML, idx, m);
    float z = ((i == j) ? 2.0f * ALPHA : 0.0f) - ALPHA * ALPHA * m;
    g_Zf[0][idx] = z;
    split_store(g_ZH[0], g_ZL[0], idx, z);
    split_store(g_ZTH[0], g_ZTL[0], (size_t)j * NXI + i, z);
}
__global__ void build_WpreSplit(const float* __restrict__ D12) {
    int idx = blockIdx.x * blockDim.x + threadIdx.x;
    if (idx >= LDIM * 640) return;
    int rr = idx / 640, c = idx - rr * 640;
    float v = (c < NXI) ? -g_H[(size_t)(NXI + rr) * HDIM + c] : D12[rr * NSTATES + (c - NXI)];
    int dc = (c < NXI) ? c : c + 128;
    split_store(g_WpreH, g_WpreL, (size_t)rr * 768 + dc, v);
}
__global__ void build_D11() {
    int idx = blockIdx.x * blockDim.x + threadIdx.x;
    if (idx >= LDIM * LDIM) return;
    int i = idx >> 7, j = idx & 127;
    g_D11[idx] = (j < i) ? -g_H[(size_t)(NXI + i) * HDIM + NXI + j] : 0.0f;
    if (j == i) g_LamInv[i] = 2.0f / g_H[(size_t)(NXI + i) * HDIM + NXI + i];
}
__global__ void build_Rt(const float* __restrict__ B2) {
    int idx = blockIdx.x * blockDim.x + threadIdx.x;
    if (idx >= NXI * 768) return;
    int i = idx / 768, c = idx - i * 768;
    float v = (c < 640) ? g_H[(size_t)(640 + i) * HDIM + c] : B2[i * NSTATES + (c - 640)];
    split_store(g_RtH, g_RtL, (size_t)c * NXI + i, g_dinv[i] * v);
}
__global__ void build_WoutTop(const float* __restrict__ C2, const float* __restrict__ D21,
                              const float* __restrict__ D22) {
    int idx = blockIdx.x * blockDim.x + threadIdx.x;
    if (idx >= NIN * 768) return;
    int rr = idx / 768, c = idx - rr * 768;
    float v = (c < NXI) ? C2[rr * NXI + c]
                        : (c < 640 ? D21[rr * LDIM + (c - NXI)] : D22[rr * NSTATES + (c - 640)]);
    split_store(g_WoutH, g_WoutL, idx, v);
}
__global__ void conv_A(const float* __restrict__ xi, const float* __restrict__ w) {
    size_t idx = (size_t)blockIdx.x * blockDim.x + threadIdx.x;
    size_t b = idx / 160;
    int c0 = (int)(idx - b * 160) * 4;
    if (b >= BATCHN) return;
    float4 v;
    int dc;
    if (c0 < NXI) { v = *(const float4*)(xi + b * NXI + c0); dc = c0; }
    else          { v = *(const float4*)(w + b * NSTATES + (c0 - NXI)); dc = c0 + 128; }
    size_t o = b * 768 + dc;
    split_store(g_AH, g_AL, o + 0, v.x);
    split_store(g_AH, g_AL, o + 1, v.y);
    split_store(g_AH, g_AL, o + 2, v.z);
    split_store(g_AH, g_AL, o + 3, v.w);
}

// ---------------- tanh forward-substitution scan ----------------
__global__ __launch_bounds__(64) void eps_kernel() {
    __shared__ float es[128 * 64];
    __shared__ float li[128];
    int tid = threadIdx.x;
    size_t b = (size_t)blockIdx.x * 64 + tid;
    for (int i = tid; i < 128; i += 64) li[i] = g_LamInv[i];
    __syncthreads();
    for (int i = 0; i < 128; ++i) {
        float v = g_pre[b * 128 + i];
        const float* __restrict__ dr = &g_D11[i * 128];
        float v0 = 0.f, v1 = 0.f, v2 = 0.f, v3 = 0.f;
        int j = 0;
        for (; j + 3 < i; j += 4) {
            v0 = fmaf(es[(j + 0) * 64 + tid], dr[j + 0], v0);
            v1 = fmaf(es[(j + 1) * 64 + tid], dr[j + 1], v1);
            v2 = fmaf(es[(j + 2) * 64 + tid], dr[j + 2], v2);
            v3 = fmaf(es[(j + 3) * 64 + tid], dr[j + 3], v3);
        }
        for (; j < i; ++j) v0 = fmaf(es[j * 64 + tid], dr[j], v0);
        v += (v0 + v1) + (v2 + v3);
        es[i * 64 + tid] = tanhf(v * li[i]);
    }
    for (int i = 0; i < 128; ++i)
        split_store(g_AH, g_AL, b * 768 + 512 + i, es[i * 64 + tid]);
}

// ---------------- launch ----------------
extern "C" void kernel_launch(void* const* d_in, const int* in_sizes, int n_in,
                              void* d_out, int out_size) {
    (void)in_sizes; (void)n_in; (void)out_size;
    const float* w   = (const float*)d_in[1];
    const float* xi  = (const float*)d_in[2];
    const float* X   = (const float*)d_in[3];
    const float* Y   = (const float*)d_in[4];
    const float* B2  = (const float*)d_in[5];
    const float* C2  = (const float*)d_in[6];
    const float* D21 = (const float*)d_in[7];
    const float* D22 = (const float*)d_in[8];
    const float* D12 = (const float*)d_in[9];
    float* out   = (float*)d_out;
    float* out_u = out;
    float* out_x = out + (size_t)BATCHN * NIN;

    static cudaStream_t s2;
    static cudaEvent_t evStart, evH, evJoin;
    static bool inited = false;
    if (!inited) {
        cudaStreamCreateWithFlags(&s2, cudaStreamNonBlocking);
        cudaEventCreateWithFlags(&evStart, cudaEventDisableTiming);
        cudaEventCreateWithFlags(&evH, cudaEventDisableTiming);
        cudaEventCreateWithFlags(&evJoin, cudaEventDisableTiming);
        cudaFuncSetAttribute(mma_gemm<3>, cudaFuncAttributeMaxDynamicSharedMemorySize, 2 * 40960);
        cudaFuncSetAttribute(mma_gemm<2>, cudaFuncAttributeMaxDynamicSharedMemorySize, 2 * 30720);
        inited = true;
    }

    float *pH, *pPre;
    __half *pAH, *pAL, *pWpreH, *pWpreL, *pWoutH, *pWoutL;
    __half *pXtH, *pXtL, *pZH1, *pZL1, *pRtH, *pRtL;
    cudaGetSymbolAddress((void**)&pH, g_H);
    cudaGetSymbolAddress((void**)&pPre, g_pre);
    cudaGetSymbolAddress((void**)&pAH, g_AH);
    cudaGetSymbolAddress((void**)&pAL, g_AL);
    cudaGetSymbolAddress((void**)&pWpreH, g_WpreH);
    cudaGetSymbolAddress((void**)&pWpreL, g_WpreL);
    cudaGetSymbolAddress((void**)&pWoutH, g_WoutH);
    cudaGetSymbolAddress((void**)&pWoutL, g_WoutL);
    cudaGetSymbolAddress((void**)&pXtH, g_XtH);
    cudaGetSymbolAddress((void**)&pXtL, g_XtL);
    cudaGetSymbolAddress((void**)&pRtH, g_RtH);
    cudaGetSymbolAddress((void**)&pRtL, g_RtL);
    {
        __half* t2;
        const int fin = NEWTON_ITERS & 1;   // final Z buffer index
        cudaGetSymbolAddress((void**)&t2, g_ZH); pZH1 = t2 + (size_t)fin * NXI * NXI;
        cudaGetSymbolAddress((void**)&t2, g_ZL); pZL1 = t2 + (size_t)fin * NXI * NXI;
    }

    // ---- top fork: conv_A on s2 in parallel with Xt/H on s0 ----
    cudaEventRecord(evStart, 0);
    cudaStreamWaitEvent(s2, evStart, 0);
    conv_A<<<(BATCHN * 160 + 255) / 256, 256, 0, s2>>>(xi, w);

    conv_Xt<<<dim3(HDIM / 32, HDIM / 32), dim3(32, 8)>>>(X);
    tc2<<<dim3(HDIM / 64, HDIM / 64), 128>>>(
        pXtH, pXtL, pXtH, pXtL, HDIM, HDIM, HDIM,
        pH, HDIM, nullptr, nullptr, 0);
    cudaEventRecord(evH, 0);
    cudaStreamWaitEvent(s2, evH, 0);

    // ---- branch B (s0, issued first so Newton CTAs claim SMs): builders -> fused Newton -> solve ----
    diag_kernel<<<2, 256>>>();
    build_MZ<<<(NXI * NXI + 255) / 256, 256>>>(Y);
    build_Rt<<<(NXI * 768 + 255) / 256, 256>>>(B2);
    build_WoutTop<<<(NIN * 768 + 255) / 256, 256>>>(C2, D21, D22);
    newton_fused<<<NWT_BLOCKS, 128>>>();
    // Wout rows 64..575 = Einv @ [Fm|B1|B2], written directly as fp16 splits
    tc2<<<dim3(768 / 64, NXI / 64), 128>>>(
        pZH1, pZL1, pRtH, pRtL, NXI, NXI, NXI,
        nullptr, 768, pWoutH + 64 * 768, pWoutL + 64 * 768, 3);

    // ---- branch A (s2): Wpre/D11 -> pre-GEMM (3-product) -> eps ----
    build_WpreSplit<<<(LDIM * 640 + 255) / 256, 256, 0, s2>>>(D12);
    build_D11<<<(LDIM * LDIM + 255) / 256, 256, 0, s2>>>();
    mma_gemm<3><<<dim3(1, BATCHN / 128), 256, 2 * 40960, s2>>>(
        pAH, pAL, pWpreH, pWpreL, 20, 512, 128, 768, 768, pPre, nullptr, 0);
    eps_kernel<<<BATCHN / 64, 64, 0, s2>>>();
    cudaEventRecord(evJoin, s2);

    // ---- join ----
    cudaStreamWaitEvent(0, evJoin, 0);

    // [u | xi_] = [xi|eps|w] @ Wout^T  (2-product fp16 split)
    mma_gemm<2><<<dim3(5, BATCHN / 128), 256, 2 * 30720>>>(
        pAH, pAL, pWoutH, pWoutL, 24, 1 << 30, 0, 768, 768, out_u, out_x, 1);
}